// round 2
// baseline (speedup 1.0000x reference)
#include <cuda_runtime.h>

// ---------------------------------------------------------------------------
// RT1Transformer fp32 forward, round 2: packed f32x2 FMA everywhere hot.
// D=512, H=8 (dh=64), L=4, V=256, B=32, S=584 (prefix 518 + 66 action).
// fma.rn.f32x2 (Blackwell packed fp32) doubles the fp32 FMA issue width.
// ---------------------------------------------------------------------------

#define NEG_BIG (-1e9f)

typedef unsigned long long u64;

constexpr int D_  = 512;
constexpr int DH_ = 64;
constexpr int NH_ = 8;
constexpr int NL_ = 4;
constexpr int VV_ = 256;
constexpr int BB_ = 32;
constexpr int KT_ = 32;
constexpr int VT_ = 486;
constexpr int AT_ = 66;
constexpr int SS_ = KT_ + VT_ + AT_;   // 584
constexpr int PP_ = KT_ + VT_;         // 518
constexpr int RR_ = BB_ * SS_;         // 18688 token rows

// scratch (static device globals; no runtime allocation allowed)
__device__ float g_x   [(size_t)RR_ * D_];
__device__ float g_qkv [(size_t)RR_ * 3 * D_];
__device__ float g_att [(size_t)RR_ * D_];
__device__ float g_tmp [(size_t)RR_ * D_];
__device__ float g_h1  [(size_t)RR_ * 4 * D_];
__device__ float g_xact[(size_t)BB_ * AT_ * D_];

// ---- packed f32x2 helpers --------------------------------------------------
__device__ __forceinline__ u64 pack2(float x, float y) {
    u64 r; asm("mov.b64 %0, {%1, %2};" : "=l"(r) : "f"(x), "f"(y)); return r;
}
__device__ __forceinline__ u64 bcast2(float x) {
    u64 r; asm("mov.b64 %0, {%1, %1};" : "=l"(r) : "f"(x)); return r;
}
__device__ __forceinline__ float2 unpack2(u64 v) {
    float2 f; asm("mov.b64 {%0, %1}, %2;" : "=f"(f.x), "=f"(f.y) : "l"(v)); return f;
}
__device__ __forceinline__ void ffma2(u64& d, u64 a, u64 b) {
    asm("fma.rn.f32x2 %0, %1, %2, %0;" : "+l"(d) : "l"(a), "l"(b));
}
__device__ __forceinline__ u64 fmul2(u64 a, u64 b) {
    u64 r; asm("mul.rn.f32x2 %0, %1, %2;" : "=l"(r) : "l"(a), "l"(b)); return r;
}

// ---------------------------------------------------------------------------
// Embed + concat: x[b,s,:] = lang | vision | action_embed[tok]
// ---------------------------------------------------------------------------
__global__ void embed_kernel(const float* __restrict__ lang,
                             const float* __restrict__ vis,
                             const int*   __restrict__ tok,
                             const float* __restrict__ emb,
                             float* __restrict__ x)
{
    int idx = blockIdx.x * blockDim.x + threadIdx.x;
    if (idx >= RR_ * (D_ / 4)) return;
    int d4  = idx % (D_ / 4);
    int row = idx / (D_ / 4);
    int b = row / SS_, s = row % SS_;
    float4 v;
    if (s < KT_) {
        v = ((const float4*)lang)[(size_t)(b * KT_ + s) * (D_ / 4) + d4];
    } else if (s < PP_) {
        v = ((const float4*)vis)[(size_t)(b * VT_ + (s - KT_)) * (D_ / 4) + d4];
    } else {
        int t = tok[b * AT_ + (s - PP_)];
        v = ((const float4*)emb)[(size_t)t * (D_ / 4) + d4];
    }
    ((float4*)x)[idx] = v;
}

// ---------------------------------------------------------------------------
// SGEMM (NT) with packed f32x2 FMA: C[m,n] = sum_k A[m,k]*B[n,k] + bias[n]
// A: MxK row-major, B: NxK row-major, N % 128 == 0, M guarded.
// 128x128x16 tile, 8x8 microtile held as 8x4 f32x2 pairs.
// ---------------------------------------------------------------------------
template<bool RELU>
__global__ __launch_bounds__(256)
void sgemm_nt(const float* __restrict__ A, const float* __restrict__ B,
              const float* __restrict__ bias, float* __restrict__ C,
              int M, int N, int K)
{
    constexpr int BM = 128, BN = 128, BK = 16;
    __shared__ __align__(16) float As[BK][BM];
    __shared__ __align__(16) float Bs[BK][BN];

    const int tid = threadIdx.x;
    const int m0 = blockIdx.y * BM;
    const int n0 = blockIdx.x * BN;
    const int tx = tid & 15;        // 8 output cols each
    const int ty = tid >> 4;        // 8 output rows each

    u64 acc[8][4];
    #pragma unroll
    for (int i = 0; i < 8; i++)
        #pragma unroll
        for (int j = 0; j < 4; j++) acc[i][j] = 0ull;   // bits of {0f,0f}

    for (int k0 = 0; k0 < K; k0 += BK) {
        #pragma unroll
        for (int it = 0; it < 2; it++) {
            int id  = tid + 256 * it;       // 0..511
            int row = id >> 2;              // 0..127
            int kq  = (id & 3) << 2;        // 0,4,8,12
            float4 va = make_float4(0.f, 0.f, 0.f, 0.f);
            if (m0 + row < M)
                va = *(const float4*)(A + (size_t)(m0 + row) * K + k0 + kq);
            As[kq + 0][row] = va.x; As[kq + 1][row] = va.y;
            As[kq + 2][row] = va.z; As[kq + 3][row] = va.w;
            float4 vb = *(const float4*)(B + (size_t)(n0 + row) * K + k0 + kq);
            Bs[kq + 0][row] = vb.x; Bs[kq + 1][row] = vb.y;
            Bs[kq + 2][row] = vb.z; Bs[kq + 3][row] = vb.w;
        }
        __syncthreads();

        #pragma unroll
        for (int kk = 0; kk < BK; kk++) {
            float a[8];
            *(float4*)&a[0] = *(const float4*)&As[kk][ty * 8];
            *(float4*)&a[4] = *(const float4*)&As[kk][ty * 8 + 4];
            u64 bv[4];
            #pragma unroll
            for (int j = 0; j < 4; j++)
                bv[j] = *(const u64*)&Bs[kk][tx * 8 + 2 * j];
            #pragma unroll
            for (int i = 0; i < 8; i++) {
                u64 av = bcast2(a[i]);
                #pragma unroll
                for (int j = 0; j < 4; j++)
                    ffma2(acc[i][j], av, bv[j]);
            }
        }
        __syncthreads();
    }

    const float* bp = bias + n0 + tx * 8;
    float bl[8];
    #pragma unroll
    for (int j = 0; j < 8; j += 4)
        *(float4*)&bl[j] = *(const float4*)(bp + j);

    #pragma unroll
    for (int i = 0; i < 8; i++) {
        int m = m0 + ty * 8 + i;
        if (m < M) {
            float* crow = C + (size_t)m * N + n0 + tx * 8;
            #pragma unroll
            for (int j = 0; j < 8; j += 4) {
                float2 p0 = unpack2(acc[i][j / 2]);
                float2 p1 = unpack2(acc[i][j / 2 + 1]);
                float4 v;
                v.x = p0.x + bl[j + 0];
                v.y = p0.y + bl[j + 1];
                v.z = p1.x + bl[j + 2];
                v.w = p1.y + bl[j + 3];
                if (RELU) {
                    v.x = fmaxf(v.x, 0.f); v.y = fmaxf(v.y, 0.f);
                    v.z = fmaxf(v.z, 0.f); v.w = fmaxf(v.w, 0.f);
                }
                *(float4*)(crow + j) = v;
            }
        }
    }
}

// ---------------------------------------------------------------------------
// Flash attention, fp32 with f32x2 inner loops.
// Block = 16 q-rows of one (b,h). 128 threads, thread (ql=tid/8, s=tid%8).
// QK^T: pairs along d. PV: pairs along output dim, P pre-broadcast as u64.
// ---------------------------------------------------------------------------
constexpr int AQ  = 16;
constexpr int AK  = 64;
constexpr int DHP = 68;   // padded row stride: 16B-aligned, conflict-free

__global__ __launch_bounds__(128)
void attn_kernel(const float* __restrict__ qkv, float* __restrict__ out)
{
    __shared__ __align__(16) float Qs[AQ][DHP];
    __shared__ __align__(16) float Ks[AK][DHP];
    __shared__ __align__(16) float Vs[AK][DHP];
    __shared__ __align__(16) u64   Ps[AQ][AK + 1];   // packed {p,p}

    const int tid = threadIdx.x;
    const int bh  = blockIdx.y;
    const int b   = bh >> 3;
    const int h   = bh & 7;
    const int q0  = blockIdx.x * AQ;
    const int ql  = tid >> 3;
    const int s   = tid & 7;
    const int qg  = q0 + ql;

    #pragma unroll
    for (int it = 0; it < 2; it++) {
        int id  = tid + 128 * it;
        int row = id >> 4;
        int dq  = (id & 15) << 2;
        float4 v = make_float4(0.f, 0.f, 0.f, 0.f);
        int rq = q0 + row;
        if (rq < SS_)
            v = *(const float4*)(qkv + (size_t)(b * SS_ + rq) * 3 * D_ + h * DH_ + dq);
        *(float4*)&Qs[row][dq] = v;
    }

    float m = -3e38f, lsum = 0.f;
    u64 o2[4];
    #pragma unroll
    for (int j = 0; j < 4; j++) o2[j] = 0ull;

    int hi = q0 + AQ; if (hi > SS_) hi = SS_;
    const int limit  = (PP_ > hi) ? PP_ : hi;
    const int ntiles = (limit + AK - 1) / AK;

    for (int t = 0; t < ntiles; t++) {
        const int kt0 = t * AK;
        #pragma unroll
        for (int it = 0; it < 8; it++) {
            int id  = tid + 128 * it;     // 0..1023
            int row = id >> 4;
            int dq  = (id & 15) << 2;
            int rk  = kt0 + row;
            float4 vk = make_float4(0.f, 0.f, 0.f, 0.f), vv = vk;
            if (rk < SS_) {
                const float* base = qkv + (size_t)(b * SS_ + rk) * 3 * D_ + h * DH_ + dq;
                vk = *(const float4*)(base + D_);
                vv = *(const float4*)(base + 2 * D_);
            }
            *(float4*)&Ks[row][dq] = vk;
            *(float4*)&Vs[row][dq] = vv;
        }
        __syncthreads();

        // ---- scores (pairs along d) ----
        u64 accs[8];
        #pragma unroll
        for (int jj = 0; jj < 8; jj++) accs[jj] = 0ull;
        #pragma unroll 4
        for (int d = 0; d < DH_; d += 4) {
            u64 q01 = *(const u64*)&Qs[ql][d];
            u64 q23 = *(const u64*)&Qs[ql][d + 2];
            #pragma unroll
            for (int jj = 0; jj < 8; jj++) {
                const float* kr = &Ks[s + 8 * jj][d];
                ffma2(accs[jj], q01, *(const u64*)kr);
                ffma2(accs[jj], q23, *(const u64*)(kr + 2));
            }
        }
        float sc[8];
        float tmax = -3e38f;
        #pragma unroll
        for (int jj = 0; jj < 8; jj++) {
            float2 f = unpack2(accs[jj]);
            int j = kt0 + s + 8 * jj;
            bool allowed = ((j < PP_) || (j <= qg)) && (j < SS_);
            sc[jj] = allowed ? (f.x + f.y) * 0.125f : NEG_BIG;
            tmax = fmaxf(tmax, sc[jj]);
        }
        tmax = fmaxf(tmax, __shfl_xor_sync(0xffffffffu, tmax, 1));
        tmax = fmaxf(tmax, __shfl_xor_sync(0xffffffffu, tmax, 2));
        tmax = fmaxf(tmax, __shfl_xor_sync(0xffffffffu, tmax, 4));
        float mnew  = fmaxf(m, tmax);
        float alpha = __expf(m - mnew);
        float psum = 0.f;
        #pragma unroll
        for (int jj = 0; jj < 8; jj++) {
            float p = __expf(sc[jj] - mnew);
            Ps[ql][s + 8 * jj] = bcast2(p);
            psum += p;
        }
        psum += __shfl_xor_sync(0xffffffffu, psum, 1);
        psum += __shfl_xor_sync(0xffffffffu, psum, 2);
        psum += __shfl_xor_sync(0xffffffffu, psum, 4);
        lsum = lsum * alpha + psum;
        m = mnew;
        __syncwarp();

        // ---- O += P @ V  (pairs along output dim) ----
        u64 al = bcast2(alpha);
        #pragma unroll
        for (int j = 0; j < 4; j++) o2[j] = fmul2(o2[j], al);
        #pragma unroll 8
        for (int k = 0; k < AK; k++) {
            u64 pv = Ps[ql][k];
            const float* vr = &Vs[k][s * 8];
            #pragma unroll
            for (int j = 0; j < 4; j++)
                ffma2(o2[j], pv, *(const u64*)(vr + 2 * j));
        }
        __syncthreads();
    }

    if (qg < SS_) {
        float inv = 1.f / lsum;
        float* op = out + (size_t)(b * SS_ + qg) * D_ + h * DH_ + s * 8;
        #pragma unroll
        for (int j = 0; j < 4; j++) {
            float2 f = unpack2(o2[j]);
            op[2 * j + 0] = f.x * inv;
            op[2 * j + 1] = f.y * inv;
        }
    }
}

// ---------------------------------------------------------------------------
// x = LayerNorm(x + t) * g + b   (one warp per row of 512)
// ---------------------------------------------------------------------------
__global__ __launch_bounds__(256)
void add_ln_kernel(float* __restrict__ x, const float* __restrict__ t,
                   const float* __restrict__ g, const float* __restrict__ bta)
{
    int row  = (blockIdx.x * blockDim.x + threadIdx.x) >> 5;
    int lane = threadIdx.x & 31;
    if (row >= RR_) return;
    float* xr = x + (size_t)row * D_;
    const float* tr = t + (size_t)row * D_;
    float v[16];
    float s = 0.f;
    #pragma unroll
    for (int i = 0; i < 16; i++) {
        int d = lane + 32 * i;
        v[i] = xr[d] + tr[d];
        s += v[i];
    }
    #pragma unroll
    for (int off = 16; off > 0; off >>= 1)
        s += __shfl_xor_sync(0xffffffffu, s, off);
    float mu = s * (1.f / D_);
    float s2 = 0.f;
    #pragma unroll
    for (int i = 0; i < 16; i++) {
        float dd = v[i] - mu;
        s2 += dd * dd;
    }
    #pragma unroll
    for (int off = 16; off > 0; off >>= 1)
        s2 += __shfl_xor_sync(0xffffffffu, s2, off);
    float r = rsqrtf(s2 * (1.f / D_) + 1e-5f);
    #pragma unroll
    for (int i = 0; i < 16; i++) {
        int d = lane + 32 * i;
        xr[d] = (v[i] - mu) * r * g[d] + bta[d];
    }
}

// ---------------------------------------------------------------------------
__global__ void gather_act(const float* __restrict__ x, float* __restrict__ xa)
{
    int idx = blockIdx.x * blockDim.x + threadIdx.x;
    const int total = BB_ * AT_ * (D_ / 4);
    if (idx >= total) return;
    int d4 = idx % (D_ / 4);
    int r  = idx / (D_ / 4);
    int b = r / AT_, a = r % AT_;
    ((float4*)xa)[idx] =
        ((const float4*)x)[(size_t)(b * SS_ + PP_ + a) * (D_ / 4) + d4];
}

// ---------------------------------------------------------------------------
extern "C" void kernel_launch(void* const* d_in, const int* in_sizes, int n_in,
                              void* d_out, int out_size)
{
    const float* lang = (const float*)d_in[0];
    const float* vis  = (const float*)d_in[1];
    const int*   tok  = (const int*)  d_in[2];
    const float* emb  = (const float*)d_in[3];
    const float* Wqkv = (const float*)d_in[4];
    const float* bqkv = (const float*)d_in[5];
    const float* Wo   = (const float*)d_in[6];
    const float* bo   = (const float*)d_in[7];
    const float* W1   = (const float*)d_in[8];
    const float* b1   = (const float*)d_in[9];
    const float* W2   = (const float*)d_in[10];
    const float* b2   = (const float*)d_in[11];
    const float* ln1g = (const float*)d_in[12];
    const float* ln1b = (const float*)d_in[13];
    const float* ln2g = (const float*)d_in[14];
    const float* ln2b = (const float*)d_in[15];
    const float* hW   = (const float*)d_in[16];
    const float* hb   = (const float*)d_in[17];
    float* out = (float*)d_out;

    float *x, *qkv, *att, *tmp, *h1, *xa;
    cudaGetSymbolAddress((void**)&x,   g_x);
    cudaGetSymbolAddress((void**)&qkv, g_qkv);
    cudaGetSymbolAddress((void**)&att, g_att);
    cudaGetSymbolAddress((void**)&tmp, g_tmp);
    cudaGetSymbolAddress((void**)&h1,  g_h1);
    cudaGetSymbolAddress((void**)&xa,  g_xact);

    embed_kernel<<<(RR_ * (D_ / 4) + 255) / 256, 256>>>(lang, vis, tok, emb, x);

    for (int l = 0; l < NL_; l++) {
        sgemm_nt<false><<<dim3(3 * D_ / 128, RR_ / 128), 256>>>(
            x, Wqkv + (size_t)l * 3 * D_ * D_, bqkv + (size_t)l * 3 * D_,
            qkv, RR_, 3 * D_, D_);
        attn_kernel<<<dim3((SS_ + AQ - 1) / AQ, BB_ * NH_), 128>>>(qkv, att);
        sgemm_nt<false><<<dim3(D_ / 128, RR_ / 128), 256>>>(
            att, Wo + (size_t)l * D_ * D_, bo + (size_t)l * D_,
            tmp, RR_, D_, D_);
        add_ln_kernel<<<(RR_ + 7) / 8, 256>>>(x, tmp, ln1g + (size_t)l * D_, ln1b + (size_t)l * D_);
        sgemm_nt<true><<<dim3(4 * D_ / 128, RR_ / 128), 256>>>(
            x, W1 + (size_t)l * 4 * D_ * D_, b1 + (size_t)l * 4 * D_,
            h1, RR_, 4 * D_, D_);
        sgemm_nt<false><<<dim3(D_ / 128, RR_ / 128), 256>>>(
            h1, W2 + (size_t)l * D_ * 4 * D_, b2 + (size_t)l * D_,
            tmp, RR_, D_, 4 * D_);
        add_ln_kernel<<<(RR_ + 7) / 8, 256>>>(x, tmp, ln2g + (size_t)l * D_, ln2b + (size_t)l * D_);
    }

    gather_act<<<(BB_ * AT_ * (D_ / 4) + 255) / 256, 256>>>(x, xa);
    sgemm_nt<false><<<dim3(VV_ / 128, (BB_ * AT_ + 127) / 128), 256>>>(
        xa, hW, hb, out, BB_ * AT_, VV_, D_);
}

// round 3
// speedup vs baseline: 1.6178x; 1.6178x over previous
#include <cuda_runtime.h>

// ---------------------------------------------------------------------------
// RT1Transformer fp32, round 3.
//  - sgemm_nt: f32x2 FMA, pair-strided B fragment (conflict-free LDS), padded
//    smem tiles (stride 132) to de-conflict the store phase.
//  - attn v3: 64q x 64k tiles, 256 threads, 4q x 4k / 4q x 4d microtiles,
//    outer-product f32x2 in both phases, packed-u64 P tile, online softmax.
// ---------------------------------------------------------------------------

#define NEG_BIG (-1e9f)

typedef unsigned long long u64;
typedef unsigned int u32;

constexpr int D_  = 512;
constexpr int DH_ = 64;
constexpr int NH_ = 8;
constexpr int NL_ = 4;
constexpr int VV_ = 256;
constexpr int BB_ = 32;
constexpr int KT_ = 32;
constexpr int VT_ = 486;
constexpr int AT_ = 66;
constexpr int SS_ = KT_ + VT_ + AT_;   // 584
constexpr int PP_ = KT_ + VT_;         // 518
constexpr int RR_ = BB_ * SS_;         // 18688

__device__ float g_x   [(size_t)RR_ * D_];
__device__ float g_qkv [(size_t)RR_ * 3 * D_];
__device__ float g_att [(size_t)RR_ * D_];
__device__ float g_tmp [(size_t)RR_ * D_];
__device__ float g_h1  [(size_t)RR_ * 4 * D_];
__device__ float g_xact[(size_t)BB_ * AT_ * D_];

// ---- packed f32x2 helpers --------------------------------------------------
__device__ __forceinline__ u64 bcast2(float x) {
    u64 r; asm("mov.b64 %0, {%1, %1};" : "=l"(r) : "f"(x)); return r;
}
__device__ __forceinline__ float2 unpack2(u64 v) {
    float2 f; asm("mov.b64 {%0, %1}, %2;" : "=f"(f.x), "=f"(f.y) : "l"(v)); return f;
}
__device__ __forceinline__ void ffma2(u64& d, u64 a, u64 b) {
    asm("fma.rn.f32x2 %0, %1, %2, %0;" : "+l"(d) : "l"(a), "l"(b));
}
__device__ __forceinline__ u64 fmul2(u64 a, u64 b) {
    u64 r; asm("mul.rn.f32x2 %0, %1, %2;" : "=l"(r) : "l"(a), "l"(b)); return r;
}
// shared-memory primitives on u32 shared addresses (no cvta per access)
__device__ __forceinline__ void lds128u(u64& a, u64& b, u32 addr) {
    asm volatile("ld.shared.v2.u64 {%0, %1}, [%2];" : "=l"(a), "=l"(b) : "r"(addr));
}
__device__ __forceinline__ u64 lds64u(u32 addr) {
    u64 r; asm volatile("ld.shared.u64 %0, [%1];" : "=l"(r) : "r"(addr)); return r;
}
__device__ __forceinline__ void sts64u(u32 addr, u64 v) {
    asm volatile("st.shared.u64 [%0], %1;" :: "r"(addr), "l"(v));
}

// ---------------------------------------------------------------------------
// Embed + concat
// ---------------------------------------------------------------------------
__global__ void embed_kernel(const float* __restrict__ lang,
                             const float* __restrict__ vis,
                             const int*   __restrict__ tok,
                             const float* __restrict__ emb,
                             float* __restrict__ x)
{
    int idx = blockIdx.x * blockDim.x + threadIdx.x;
    if (idx >= RR_ * (D_ / 4)) return;
    int d4  = idx % (D_ / 4);
    int row = idx / (D_ / 4);
    int b = row / SS_, s = row % SS_;
    float4 v;
    if (s < KT_) {
        v = ((const float4*)lang)[(size_t)(b * KT_ + s) * (D_ / 4) + d4];
    } else if (s < PP_) {
        v = ((const float4*)vis)[(size_t)(b * VT_ + (s - KT_)) * (D_ / 4) + d4];
    } else {
        int t = tok[b * AT_ + (s - PP_)];
        v = ((const float4*)emb)[(size_t)t * (D_ / 4) + d4];
    }
    ((float4*)x)[idx] = v;
}

// ---------------------------------------------------------------------------
// SGEMM (NT), f32x2, conflict-tuned. C[m,n] = sum_k A[m,k]B[n,k] + bias[n].
// N % 128 == 0, M guarded. Thread owns rows ty*8..+8, col pairs {2tx+32j,+1}.
// ---------------------------------------------------------------------------
template<bool RELU>
__global__ __launch_bounds__(256)
void sgemm_nt(const float* __restrict__ A, const float* __restrict__ B,
              const float* __restrict__ bias, float* __restrict__ C,
              int M, int N, int K)
{
    constexpr int BM = 128, BN = 128, BK = 16, LDP = 132;
    __shared__ __align__(16) float As[BK * LDP];
    __shared__ __align__(16) float Bs[BK * LDP];

    const int tid = threadIdx.x;
    const int m0 = blockIdx.y * BM;
    const int n0 = blockIdx.x * BN;
    const int tx = tid & 15;
    const int ty = tid >> 4;

    u64 acc[8][4];
    #pragma unroll
    for (int i = 0; i < 8; i++)
        #pragma unroll
        for (int j = 0; j < 4; j++) acc[i][j] = 0ull;

    for (int k0 = 0; k0 < K; k0 += BK) {
        #pragma unroll
        for (int it = 0; it < 2; it++) {
            int id  = tid + 256 * it;
            int row = id >> 2;
            int kq  = (id & 3) << 2;
            float4 va = make_float4(0.f, 0.f, 0.f, 0.f);
            if (m0 + row < M)
                va = *(const float4*)(A + (size_t)(m0 + row) * K + k0 + kq);
            As[(kq + 0) * LDP + row] = va.x; As[(kq + 1) * LDP + row] = va.y;
            As[(kq + 2) * LDP + row] = va.z; As[(kq + 3) * LDP + row] = va.w;
            float4 vb = *(const float4*)(B + (size_t)(n0 + row) * K + k0 + kq);
            Bs[(kq + 0) * LDP + row] = vb.x; Bs[(kq + 1) * LDP + row] = vb.y;
            Bs[(kq + 2) * LDP + row] = vb.z; Bs[(kq + 3) * LDP + row] = vb.w;
        }
        __syncthreads();

        #pragma unroll
        for (int kk = 0; kk < BK; kk++) {
            float a[8];
            *(float4*)&a[0] = *(const float4*)&As[kk * LDP + ty * 8];
            *(float4*)&a[4] = *(const float4*)&As[kk * LDP + ty * 8 + 4];
            u64 bv[4];
            #pragma unroll
            for (int j = 0; j < 4; j++)
                bv[j] = *(const u64*)&Bs[kk * LDP + 2 * tx + 32 * j];
            #pragma unroll
            for (int i = 0; i < 8; i++) {
                u64 av = bcast2(a[i]);
                #pragma unroll
                for (int j = 0; j < 4; j++)
                    ffma2(acc[i][j], av, bv[j]);
            }
        }
        __syncthreads();
    }

    #pragma unroll
    for (int j = 0; j < 4; j++) {
        int n = n0 + 2 * tx + 32 * j;
        float2 bb = *(const float2*)(bias + n);
        #pragma unroll
        for (int i = 0; i < 8; i++) {
            int m = m0 + ty * 8 + i;
            if (m < M) {
                float2 f = unpack2(acc[i][j]);
                f.x += bb.x; f.y += bb.y;
                if (RELU) { f.x = fmaxf(f.x, 0.f); f.y = fmaxf(f.y, 0.f); }
                *(float2*)(C + (size_t)m * N + n) = f;
            }
        }
    }
}

// ---------------------------------------------------------------------------
// Flash attention v3. Block: 64 q-rows of one (b,h), 256 threads.
// Thread (tx=tid&15, ty=tid>>4):
//   scores: owns S[4q][4k], q rows 4ty+i, k rows tx+16j (strided).
//   PV:     owns O[4q][4d], d cols 4tx..+3.
// Dynamic smem: Qs[64][68], Ks[64][68], Vs[64][68] fp32; Ps[64][66] u64
// (P pre-packed {p,p} at write time).
// ---------------------------------------------------------------------------
constexpr int BQ  = 64;
constexpr int BKT = 64;
constexpr int AT_SMEM = (3 * 64 * 68) * 4 + 64 * 66 * 8;   // 86016 B

__global__ __launch_bounds__(256, 2)
void attn_kernel(const float* __restrict__ qkv, float* __restrict__ out)
{
    extern __shared__ __align__(16) float sm[];
    float* Qs = sm;                      // [64][68]
    float* Ks = sm + 64 * 68;            // [64][68]
    float* Vs = sm + 2 * 64 * 68;        // [64][68]
    u64*   Ps = (u64*)(sm + 3 * 64 * 68);// [64][66]

    const u32 qsb = (u32)__cvta_generic_to_shared(Qs);
    const u32 ksb = (u32)__cvta_generic_to_shared(Ks);
    const u32 vsb = (u32)__cvta_generic_to_shared(Vs);
    const u32 psb = (u32)__cvta_generic_to_shared(Ps);

    const int tid = threadIdx.x;
    const int tx = tid & 15, ty = tid >> 4;
    const int bh = blockIdx.y, b = bh >> 3, h = bh & 7;
    const int q0 = blockIdx.x * BQ;

    // load Q tile once (zero-fill invalid rows)
    #pragma unroll
    for (int it = 0; it < 4; it++) {
        int id = tid + 256 * it;
        int r  = id >> 4;
        int dc = (id & 15) << 2;
        float4 v = make_float4(0.f, 0.f, 0.f, 0.f);
        if (q0 + r < SS_)
            v = *(const float4*)(qkv + (size_t)(b * SS_ + q0 + r) * (3 * D_) + h * DH_ + dc);
        *(float4*)&Qs[r * 68 + dc] = v;
    }

    float m[4], l[4];
    #pragma unroll
    for (int i = 0; i < 4; i++) { m[i] = -3e38f; l[i] = 0.f; }
    u64 o2[4][2];
    #pragma unroll
    for (int i = 0; i < 4; i++) { o2[i][0] = 0ull; o2[i][1] = 0ull; }

    int qhi = q0 + BQ; if (qhi > SS_) qhi = SS_;
    const int limit  = (PP_ > qhi) ? PP_ : qhi;
    const int ntiles = (limit + BKT - 1) / BKT;

    const u32 qa = qsb + (u32)ty * 1088;           // 4ty rows * 272 B
    const u32 ka = ksb + (u32)tx * 272;            // row tx, +j*16 rows
    const u32 pa = psb + (u32)ty * 2112;           // 4ty rows * 528 B
    const u32 va = vsb + (u32)tx * 16;             // col 4tx

    for (int t = 0; t < ntiles; t++) {
        const int kt0 = t * BKT;
        __syncthreads();   // previous PV readers done before overwrite
        #pragma unroll
        for (int it = 0; it < 4; it++) {
            int id = tid + 256 * it;
            int r  = id >> 4;
            int dc = (id & 15) << 2;
            int rk = kt0 + r;
            float4 vk = make_float4(0.f, 0.f, 0.f, 0.f), vv = vk;
            if (rk < SS_) {
                const float* base = qkv + (size_t)(b * SS_ + rk) * (3 * D_) + h * DH_ + dc;
                vk = *(const float4*)(base + D_);
                vv = *(const float4*)(base + 2 * D_);
            }
            *(float4*)&Ks[r * 68 + dc] = vk;
            *(float4*)&Vs[r * 68 + dc] = vv;
        }
        __syncthreads();

        // ---- scores: S = Q K^T (outer product over d, f32x2 pairs) ----
        u64 acc[4][4];
        #pragma unroll
        for (int i = 0; i < 4; i++)
            #pragma unroll
            for (int j = 0; j < 4; j++) acc[i][j] = 0ull;

        #pragma unroll 4
        for (int d = 0; d < DH_; d += 4) {
            u64 q01[4], q23[4], k01[4], k23[4];
            #pragma unroll
            for (int i = 0; i < 4; i++)
                lds128u(q01[i], q23[i], qa + (u32)i * 272 + (u32)d * 4);
            #pragma unroll
            for (int j = 0; j < 4; j++)
                lds128u(k01[j], k23[j], ka + (u32)j * 4352 + (u32)d * 4);
            #pragma unroll
            for (int i = 0; i < 4; i++)
                #pragma unroll
                for (int j = 0; j < 4; j++) {
                    ffma2(acc[i][j], q01[i], k01[j]);
                    ffma2(acc[i][j], q23[i], k23[j]);
                }
        }

        // ---- online softmax ----
        const bool masked = (kt0 + BKT > PP_);
        float alpha[4];
        float p[4][4];
        #pragma unroll
        for (int i = 0; i < 4; i++) {
            const int qg = q0 + 4 * ty + i;
            float sc[4];
            float tmax = -3e38f;
            #pragma unroll
            for (int j = 0; j < 4; j++) {
                float2 f = unpack2(acc[i][j]);
                float s = (f.x + f.y) * 0.125f;
                if (masked) {
                    int kg = kt0 + tx + 16 * j;
                    bool ok = (kg < PP_) || ((kg <= qg) && (kg < SS_));
                    if (!ok) s = NEG_BIG;
                }
                sc[j] = s;
                tmax = fmaxf(tmax, s);
            }
            tmax = fmaxf(tmax, __shfl_xor_sync(0xffffffffu, tmax, 1));
            tmax = fmaxf(tmax, __shfl_xor_sync(0xffffffffu, tmax, 2));
            tmax = fmaxf(tmax, __shfl_xor_sync(0xffffffffu, tmax, 4));
            tmax = fmaxf(tmax, __shfl_xor_sync(0xffffffffu, tmax, 8));
            float mnew = fmaxf(m[i], tmax);
            alpha[i] = __expf(m[i] - mnew);
            float ps = 0.f;
            #pragma unroll
            for (int j = 0; j < 4; j++) {
                p[i][j] = __expf(sc[j] - mnew);
                ps += p[i][j];
            }
            ps += __shfl_xor_sync(0xffffffffu, ps, 1);
            ps += __shfl_xor_sync(0xffffffffu, ps, 2);
            ps += __shfl_xor_sync(0xffffffffu, ps, 4);
            ps += __shfl_xor_sync(0xffffffffu, ps, 8);
            l[i] = l[i] * alpha[i] + ps;
            m[i] = mnew;
        }

        // store P packed {p,p} — rows 4ty+i are private to this half-warp
        #pragma unroll
        for (int i = 0; i < 4; i++)
            #pragma unroll
            for (int j = 0; j < 4; j++)
                sts64u(psb + (u32)((4 * ty + i) * 66 + tx + 16 * j) * 8,
                       bcast2(p[i][j]));
        __syncwarp();

        // ---- O = O*alpha + P V ----
        #pragma unroll
        for (int i = 0; i < 4; i++) {
            u64 av = bcast2(alpha[i]);
            o2[i][0] = fmul2(o2[i][0], av);
            o2[i][1] = fmul2(o2[i][1], av);
        }
        #pragma unroll 4
        for (int k = 0; k < BKT; k += 4) {
            u64 pv[4][4];
            #pragma unroll
            for (int i = 0; i < 4; i++)
                #pragma unroll
                for (int kk = 0; kk < 4; kk++)
                    pv[i][kk] = lds64u(pa + (u32)i * 528 + (u32)(k + kk) * 8);
            #pragma unroll
            for (int kk = 0; kk < 4; kk++) {
                u64 v01, v23;
                lds128u(v01, v23, va + (u32)(k + kk) * 272);
                #pragma unroll
                for (int i = 0; i < 4; i++) {
                    ffma2(o2[i][0], pv[i][kk], v01);
                    ffma2(o2[i][1], pv[i][kk], v23);
                }
            }
        }
    }

    #pragma unroll
    for (int i = 0; i < 4; i++) {
        int qg = q0 + 4 * ty + i;
        if (qg < SS_) {
            float inv = 1.f / l[i];
            float2 f0 = unpack2(o2[i][0]);
            float2 f1 = unpack2(o2[i][1]);
            float4 v = make_float4(f0.x * inv, f0.y * inv, f1.x * inv, f1.y * inv);
            *(float4*)(out + (size_t)(b * SS_ + qg) * D_ + h * DH_ + 4 * tx) = v;
        }
    }
}

// ---------------------------------------------------------------------------
// x = LayerNorm(x + t) * g + b   (one warp per row)
// ---------------------------------------------------------------------------
__global__ __launch_bounds__(256)
void add_ln_kernel(float* __restrict__ x, const float* __restrict__ t,
                   const float* __restrict__ g, const float* __restrict__ bta)
{
    int row  = (blockIdx.x * blockDim.x + threadIdx.x) >> 5;
    int lane = threadIdx.x & 31;
    if (row >= RR_) return;
    float* xr = x + (size_t)row * D_;
    const float* tr = t + (size_t)row * D_;
    float v[16];
    float s = 0.f;
    #pragma unroll
    for (int i = 0; i < 16; i++) {
        int d = lane + 32 * i;
        v[i] = xr[d] + tr[d];
        s += v[i];
    }
    #pragma unroll
    for (int off = 16; off > 0; off >>= 1)
        s += __shfl_xor_sync(0xffffffffu, s, off);
    float mu = s * (1.f / D_);
    float s2 = 0.f;
    #pragma unroll
    for (int i = 0; i < 16; i++) {
        float dd = v[i] - mu;
        s2 += dd * dd;
    }
    #pragma unroll
    for (int off = 16; off > 0; off >>= 1)
        s2 += __shfl_xor_sync(0xffffffffu, s2, off);
    float r = rsqrtf(s2 * (1.f / D_) + 1e-5f);
    #pragma unroll
    for (int i = 0; i < 16; i++) {
        int d = lane + 32 * i;
        xr[d] = (v[i] - mu) * r * g[d] + bta[d];
    }
}

// ---------------------------------------------------------------------------
__global__ void gather_act(const float* __restrict__ x, float* __restrict__ xa)
{
    int idx = blockIdx.x * blockDim.x + threadIdx.x;
    const int total = BB_ * AT_ * (D_ / 4);
    if (idx >= total) return;
    int d4 = idx % (D_ / 4);
    int r  = idx / (D_ / 4);
    int b = r / AT_, a = r % AT_;
    ((float4*)xa)[idx] =
        ((const float4*)x)[(size_t)(b * SS_ + PP_ + a) * (D_ / 4) + d4];
}

// ---------------------------------------------------------------------------
extern "C" void kernel_launch(void* const* d_in, const int* in_sizes, int n_in,
                              void* d_out, int out_size)
{
    const float* lang = (const float*)d_in[0];
    const float* vis  = (const float*)d_in[1];
    const int*   tok  = (const int*)  d_in[2];
    const float* emb  = (const float*)d_in[3];
    const float* Wqkv = (const float*)d_in[4];
    const float* bqkv = (const float*)d_in[5];
    const float* Wo   = (const float*)d_in[6];
    const float* bo   = (const float*)d_in[7];
    const float* W1   = (const float*)d_in[8];
    const float* b1   = (const float*)d_in[9];
    const float* W2   = (const float*)d_in[10];
    const float* b2   = (const float*)d_in[11];
    const float* ln1g = (const float*)d_in[12];
    const float* ln1b = (const float*)d_in[13];
    const float* ln2g = (const float*)d_in[14];
    const float* ln2b = (const float*)d_in[15];
    const float* hW   = (const float*)d_in[16];
    const float* hb   = (const float*)d_in[17];
    float* out = (float*)d_out;

    float *x, *qkv, *att, *tmp, *h1, *xa;
    cudaGetSymbolAddress((void**)&x,   g_x);
    cudaGetSymbolAddress((void**)&qkv, g_qkv);
    cudaGetSymbolAddress((void**)&att, g_att);
    cudaGetSymbolAddress((void**)&tmp, g_tmp);
    cudaGetSymbolAddress((void**)&h1,  g_h1);
    cudaGetSymbolAddress((void**)&xa,  g_xact);

    cudaFuncSetAttribute(attn_kernel,
                         cudaFuncAttributeMaxDynamicSharedMemorySize, AT_SMEM);

    embed_kernel<<<(RR_ * (D_ / 4) + 255) / 256, 256>>>(lang, vis, tok, emb, x);

    for (int l = 0; l < NL_; l++) {
        sgemm_nt<false><<<dim3(3 * D_ / 128, RR_ / 128), 256>>>(
            x, Wqkv + (size_t)l * 3 * D_ * D_, bqkv + (size_t)l * 3 * D_,
            qkv, RR_, 3 * D_, D_);
        attn_kernel<<<dim3((SS_ + BQ - 1) / BQ, BB_ * NH_), 256, AT_SMEM>>>(qkv, att);
        sgemm_nt<false><<<dim3(D_ / 128, RR_ / 128), 256>>>(
            att, Wo + (size_t)l * D_ * D_, bo + (size_t)l * D_,
            tmp, RR_, D_, D_);
        add_ln_kernel<<<(RR_ + 7) / 8, 256>>>(x, tmp, ln1g + (size_t)l * D_, ln1b + (size_t)l * D_);
        sgemm_nt<true><<<dim3(4 * D_ / 128, RR_ / 128), 256>>>(
            x, W1 + (size_t)l * 4 * D_ * D_, b1 + (size_t)l * 4 * D_,
            h1, RR_, 4 * D_, D_);
        sgemm_nt<false><<<dim3(D_ / 128, RR_ / 128), 256>>>(
            h1, W2 + (size_t)l * D_ * 4 * D_, b2 + (size_t)l * D_,
            tmp, RR_, D_, 4 * D_);
        add_ln_kernel<<<(RR_ + 7) / 8, 256>>>(x, tmp, ln2g + (size_t)l * D_, ln2b + (size_t)l * D_);
    }

    gather_act<<<(BB_ * AT_ * (D_ / 4) + 255) / 256, 256>>>(x, xa);
    sgemm_nt<false><<<dim3(VV_ / 128, (BB_ * AT_ + 127) / 128), 256>>>(
        xa, hW, hb, out, BB_ * AT_, VV_, D_);
}

// round 8
// speedup vs baseline: 2.8586x; 1.7670x over previous
#include <cuda_runtime.h>
#include <cuda_bf16.h>
#include <cstdint>

// ---------------------------------------------------------------------------
// RT1Transformer, round 8 (third submission of the mma.sync design; rounds
// 6/7 died to broker infra before any HW signal):
// GEMMs via mma.sync bf16 (split-bf16 3-product emulation of fp32) — the
// harness targets PTX sm_100 (no 'a'), so tcgen05 is unavailable; HMMA-path
// mma.sync is the fastest legal tensor path.
// Flash-attention kept fp32-FFMA2. Producers emit bf16 hi/lo splits.
// ---------------------------------------------------------------------------

#define NEG_BIG (-1e9f)

typedef unsigned long long u64;
typedef unsigned int u32;

constexpr int D_  = 512;
constexpr int DH_ = 64;
constexpr int NH_ = 8;
constexpr int NL_ = 4;
constexpr int VV_ = 256;
constexpr int BB_ = 32;
constexpr int KT_ = 32;
constexpr int VT_ = 486;
constexpr int AT_ = 66;
constexpr int SS_ = KT_ + VT_ + AT_;   // 584
constexpr int PP_ = KT_ + VT_;         // 518
constexpr int RR_ = BB_ * SS_;         // 18688 (= 146*128)
constexpr int MA_ = BB_ * AT_;         // 2112
constexpr int MAP_ = 17 * 128;         // 2176 padded

// fp32 scratch
__device__ float g_x   [(size_t)RR_ * D_];
__device__ float g_qkv [(size_t)RR_ * 3 * D_];
__device__ float g_tmp [(size_t)RR_ * D_];
// bf16 hi/lo activation splits
__device__ __nv_bfloat16 g_xh  [(size_t)RR_ * D_];
__device__ __nv_bfloat16 g_xl  [(size_t)RR_ * D_];
__device__ __nv_bfloat16 g_ath [(size_t)RR_ * D_];
__device__ __nv_bfloat16 g_atl [(size_t)RR_ * D_];
__device__ __nv_bfloat16 g_h1h [(size_t)RR_ * 4 * D_];
__device__ __nv_bfloat16 g_h1l [(size_t)RR_ * 4 * D_];
__device__ __nv_bfloat16 g_xah [(size_t)MAP_ * D_];   // zero-init padding rows
__device__ __nv_bfloat16 g_xal [(size_t)MAP_ * D_];
// bf16 hi/lo weights
__device__ __nv_bfloat16 g_wqh [(size_t)NL_ * 3 * D_ * D_];
__device__ __nv_bfloat16 g_wql [(size_t)NL_ * 3 * D_ * D_];
__device__ __nv_bfloat16 g_woh [(size_t)NL_ * D_ * D_];
__device__ __nv_bfloat16 g_wol [(size_t)NL_ * D_ * D_];
__device__ __nv_bfloat16 g_w1h [(size_t)NL_ * 4 * D_ * D_];
__device__ __nv_bfloat16 g_w1l [(size_t)NL_ * 4 * D_ * D_];
__device__ __nv_bfloat16 g_w2h [(size_t)NL_ * 4 * D_ * D_];
__device__ __nv_bfloat16 g_w2l [(size_t)NL_ * 4 * D_ * D_];
__device__ __nv_bfloat16 g_hwh [(size_t)VV_ * D_];
__device__ __nv_bfloat16 g_hwl [(size_t)VV_ * D_];

// ---- packed f32x2 helpers (attention) --------------------------------------
__device__ __forceinline__ u64 bcast2(float x) {
    u64 r; asm("mov.b64 %0, {%1, %1};" : "=l"(r) : "f"(x)); return r;
}
__device__ __forceinline__ float2 unpack2(u64 v) {
    float2 f; asm("mov.b64 {%0, %1}, %2;" : "=f"(f.x), "=f"(f.y) : "l"(v)); return f;
}
__device__ __forceinline__ void ffma2(u64& d, u64 a, u64 b) {
    asm("fma.rn.f32x2 %0, %1, %2, %0;" : "+l"(d) : "l"(a), "l"(b));
}
__device__ __forceinline__ u64 fmul2(u64 a, u64 b) {
    u64 r; asm("mul.rn.f32x2 %0, %1, %2;" : "=l"(r) : "l"(a), "l"(b)); return r;
}
__device__ __forceinline__ void lds128u(u64& a, u64& b, u32 addr) {
    asm volatile("ld.shared.v2.u64 {%0, %1}, [%2];" : "=l"(a), "=l"(b) : "r"(addr));
}
__device__ __forceinline__ u64 lds64u(u32 addr) {
    u64 r; asm volatile("ld.shared.u64 %0, [%1];" : "=l"(r) : "r"(addr)); return r;
}
__device__ __forceinline__ void sts64u(u32 addr, u64 v) {
    asm volatile("st.shared.u64 [%0], %1;" :: "r"(addr), "l"(v));
}

// ---- bf16 split helpers -----------------------------------------------------
__device__ __forceinline__ void split1(float v, __nv_bfloat16& h, __nv_bfloat16& l) {
    h = __float2bfloat16(v);
    l = __float2bfloat16(v - __bfloat162float(h));
}
__device__ __forceinline__ void split4(float4 v, uint2& h, uint2& l) {
    __nv_bfloat16 h0, h1, h2, h3, l0, l1, l2, l3;
    split1(v.x, h0, l0); split1(v.y, h1, l1);
    split1(v.z, h2, l2); split1(v.w, h3, l3);
    h.x = ((u32)__bfloat16_as_ushort(h1) << 16) | __bfloat16_as_ushort(h0);
    h.y = ((u32)__bfloat16_as_ushort(h3) << 16) | __bfloat16_as_ushort(h2);
    l.x = ((u32)__bfloat16_as_ushort(l1) << 16) | __bfloat16_as_ushort(l0);
    l.y = ((u32)__bfloat16_as_ushort(l3) << 16) | __bfloat16_as_ushort(l2);
}
__device__ __forceinline__ void split2(float x, float y, u32& h, u32& l) {
    __nv_bfloat16 hx, lx, hy, ly;
    split1(x, hx, lx); split1(y, hy, ly);
    h = ((u32)__bfloat16_as_ushort(hy) << 16) | __bfloat16_as_ushort(hx);
    l = ((u32)__bfloat16_as_ushort(ly) << 16) | __bfloat16_as_ushort(lx);
}

// ---- mma.sync primitives ----------------------------------------------------
__device__ __forceinline__ void ldm4(u32& r0, u32& r1, u32& r2, u32& r3, u32 a) {
    asm volatile("ldmatrix.sync.aligned.m8n8.x4.shared.b16 {%0,%1,%2,%3}, [%4];"
                 : "=r"(r0), "=r"(r1), "=r"(r2), "=r"(r3) : "r"(a));
}
__device__ __forceinline__ void mma16816(float* d, const u32* a, u32 b0, u32 b1) {
    asm volatile("mma.sync.aligned.m16n8k16.row.col.f32.bf16.bf16.f32 "
                 "{%0,%1,%2,%3}, {%4,%5,%6,%7}, {%8,%9}, {%0,%1,%2,%3};"
                 : "+f"(d[0]), "+f"(d[1]), "+f"(d[2]), "+f"(d[3])
                 : "r"(a[0]), "r"(a[1]), "r"(a[2]), "r"(a[3]), "r"(b0), "r"(b1));
}
__device__ __forceinline__ void cp16(u32 dst, const void* src) {
    asm volatile("cp.async.cg.shared.global [%0], [%1], 16;" :: "r"(dst), "l"(src));
}
__device__ __forceinline__ void cp_commit() { asm volatile("cp.async.commit_group;"); }
__device__ __forceinline__ void cp_wait1()  { asm volatile("cp.async.wait_group 1;"); }

// ---------------------------------------------------------------------------
// split-bf16 mma.sync GEMM: C[m,n] = sum_k A[m,k]B[n,k] + bias[n]
// C ~= Ah Bh^T + Ah Bl^T + Al Bh^T (fp32 accum).
// Tile 128x128, BK=64, 8 warps (4M x 2N), warp tile 32x64.
// smem rows 128B, swizzle off = row*128 + ((k ^ (row&7))*16): conflict-free.
// ---------------------------------------------------------------------------
constexpr u32 GM_TILE  = 16384;           // 128 rows x 128 B
constexpr u32 GM_STAGE = 4 * GM_TILE;     // Ah, Al, Bh, Bl
constexpr int GM_SMEM  = 1024 + 2 * (int)GM_STAGE;   // align slack + 2 stages

template<bool RELU, bool OUTBF16>
__global__ __launch_bounds__(256)
void gemm_mma(const __nv_bfloat16* __restrict__ Ah, const __nv_bfloat16* __restrict__ Al,
              const __nv_bfloat16* __restrict__ Bh, const __nv_bfloat16* __restrict__ Bl,
              const float* __restrict__ bias,
              float* __restrict__ Cf,
              __nv_bfloat16* __restrict__ Ch, __nv_bfloat16* __restrict__ Cl,
              int M, int N, int K)
{
    extern __shared__ char dynraw[];
    const u32 raw = (u32)__cvta_generic_to_shared(dynraw);
    const u32 sb  = (raw + 1023u) & ~1023u;

    const int tid  = threadIdx.x;
    const int lane = tid & 31;
    const int warp = tid >> 5;
    const int wm   = warp >> 1;     // 0..3
    const int wn   = warp & 1;      // 0..1
    const int m0 = blockIdx.y * 128;
    const int n0 = blockIdx.x * 128;

    const __nv_bfloat16* tp[4] = {Ah, Al, Bh, Bl};
    const int rb[4] = {m0, m0, n0, n0};

    float acc[2][8][4];
    #pragma unroll
    for (int i = 0; i < 2; i++)
        #pragma unroll
        for (int j = 0; j < 8; j++)
            #pragma unroll
            for (int q = 0; q < 4; q++) acc[i][j][q] = 0.f;

    // per-thread load coords: 16 chunks of 16B per stage (4 per tile)
    const int lrow = tid >> 3;           // 0..31 (+32*j)
    const int lk   = tid & 7;            // 16B chunk in row

    const int NC = K >> 6;

    // fill(stage, chunk)
    auto fill = [&](int stage, int chunk) {
        const u32 stb = sb + (u32)stage * GM_STAGE;
        const int k0 = chunk << 6;
        #pragma unroll
        for (int o = 0; o < 4; o++) {
            const __nv_bfloat16* bp = tp[o];
            const int r0 = rb[o];
            const u32 tb = stb + (u32)o * GM_TILE;
            #pragma unroll
            for (int j = 0; j < 4; j++) {
                const int row = lrow + 32 * j;
                const u32 dst = tb + (u32)(row * 128 + ((lk ^ (row & 7)) * 16));
                cp16(dst, bp + (size_t)(r0 + row) * K + k0 + lk * 8);
            }
        }
    };

    fill(0, 0); cp_commit();
    fill(1, 1); cp_commit();
    cp_wait1();
    __syncthreads();

    for (int c = 0; c < NC; c++) {
        const int s = c & 1;
        const u32 stb = sb + (u32)s * GM_STAGE;

        #pragma unroll
        for (int h = 0; h < 4; h++) {
            // A fragments (hi, lo): 2 m16 tiles
            u32 ah[2][4], al[2][4];
            #pragma unroll
            for (int i = 0; i < 2; i++) {
                const int row = wm * 32 + i * 16 + (lane & 15);
                const int ch  = 2 * h + (lane >> 4);
                const u32 off = (u32)(row * 128 + ((ch ^ (row & 7)) * 16));
                ldm4(ah[i][0], ah[i][1], ah[i][2], ah[i][3], stb + off);
                ldm4(al[i][0], al[i][1], al[i][2], al[i][3], stb + GM_TILE + off);
            }
            // B fragments (hi, lo): 8 n8 tiles via 4 x4 loads each
            u32 bh[8][2], bl[8][2];
            #pragma unroll
            for (int g = 0; g < 4; g++) {
                const int row = wn * 64 + g * 16 + (lane & 7) + ((lane >> 4) << 3);
                const int ch  = 2 * h + ((lane >> 3) & 1);
                const u32 off = (u32)(row * 128 + ((ch ^ (row & 7)) * 16));
                ldm4(bh[2 * g][0], bh[2 * g][1], bh[2 * g + 1][0], bh[2 * g + 1][1],
                     stb + 2 * GM_TILE + off);
                ldm4(bl[2 * g][0], bl[2 * g][1], bl[2 * g + 1][0], bl[2 * g + 1][1],
                     stb + 3 * GM_TILE + off);
            }
            #pragma unroll
            for (int i = 0; i < 2; i++)
                #pragma unroll
                for (int j = 0; j < 8; j++) {
                    mma16816(acc[i][j], ah[i], bh[j][0], bh[j][1]);
                    mma16816(acc[i][j], ah[i], bl[j][0], bl[j][1]);
                    mma16816(acc[i][j], al[i], bh[j][0], bh[j][1]);
                }
        }
        __syncthreads();
        if (c + 2 < NC) fill(s, c + 2);
        cp_commit();
        cp_wait1();
        __syncthreads();
    }

    // epilogue: fragment (i, j): rows m0+wm*32+i*16+lane/4 (+8), col n0+wn*64+j*8+(lane&3)*2
    #pragma unroll
    for (int i = 0; i < 2; i++) {
        const int r0 = m0 + wm * 32 + i * 16 + (lane >> 2);
        #pragma unroll
        for (int j = 0; j < 8; j++) {
            const int col = n0 + wn * 64 + j * 8 + (lane & 3) * 2;
            const float2 bb = *(const float2*)(bias + col);
            float v0 = acc[i][j][0] + bb.x, v1 = acc[i][j][1] + bb.y;
            float v2 = acc[i][j][2] + bb.x, v3 = acc[i][j][3] + bb.y;
            if (RELU) {
                v0 = fmaxf(v0, 0.f); v1 = fmaxf(v1, 0.f);
                v2 = fmaxf(v2, 0.f); v3 = fmaxf(v3, 0.f);
            }
            if (r0 < M) {
                if (OUTBF16) {
                    u32 hh, ll; split2(v0, v1, hh, ll);
                    *(u32*)(Ch + (size_t)r0 * N + col) = hh;
                    *(u32*)(Cl + (size_t)r0 * N + col) = ll;
                } else {
                    *(float2*)(Cf + (size_t)r0 * N + col) = make_float2(v0, v1);
                }
            }
            if (r0 + 8 < M) {
                if (OUTBF16) {
                    u32 hh, ll; split2(v2, v3, hh, ll);
                    *(u32*)(Ch + (size_t)(r0 + 8) * N + col) = hh;
                    *(u32*)(Cl + (size_t)(r0 + 8) * N + col) = ll;
                } else {
                    *(float2*)(Cf + (size_t)(r0 + 8) * N + col) = make_float2(v2, v3);
                }
            }
        }
    }
}

// ---------------------------------------------------------------------------
// fp32 -> (hi, lo) bf16 conversion (weights)
// ---------------------------------------------------------------------------
__global__ void conv_split(const float4* __restrict__ s, uint2* __restrict__ h,
                           uint2* __restrict__ l, int n4)
{
    int i = blockIdx.x * blockDim.x + threadIdx.x;
    if (i >= n4) return;
    uint2 hh, ll;
    split4(s[i], hh, ll);
    h[i] = hh; l[i] = ll;
}

// ---------------------------------------------------------------------------
// Embed + concat; writes x (f32) and hi/lo splits
// ---------------------------------------------------------------------------
__global__ void embed_kernel(const float* __restrict__ lang,
                             const float* __restrict__ vis,
                             const int*   __restrict__ tok,
                             const float* __restrict__ emb,
                             float* __restrict__ x,
                             __nv_bfloat16* __restrict__ xh,
                             __nv_bfloat16* __restrict__ xl)
{
    int idx = blockIdx.x * blockDim.x + threadIdx.x;
    if (idx >= RR_ * (D_ / 4)) return;
    int d4  = idx % (D_ / 4);
    int row = idx / (D_ / 4);
    int b = row / SS_, s = row % SS_;
    float4 v;
    if (s < KT_) {
        v = ((const float4*)lang)[(size_t)(b * KT_ + s) * (D_ / 4) + d4];
    } else if (s < PP_) {
        v = ((const float4*)vis)[(size_t)(b * VT_ + (s - KT_)) * (D_ / 4) + d4];
    } else {
        int t = tok[b * AT_ + (s - PP_)];
        v = ((const float4*)emb)[(size_t)t * (D_ / 4) + d4];
    }
    ((float4*)x)[idx] = v;
    uint2 hh, ll;
    split4(v, hh, ll);
    ((uint2*)xh)[idx] = hh;
    ((uint2*)xl)[idx] = ll;
}

// ---------------------------------------------------------------------------
// Flash attention (fp32 f32x2), writes bf16 hi/lo output splits.
// ---------------------------------------------------------------------------
constexpr int BQ  = 64;
constexpr int BKT = 64;
constexpr int AT_SMEM = (3 * 64 * 68) * 4 + 64 * 66 * 8;

__global__ __launch_bounds__(256, 2)
void attn_kernel(const float* __restrict__ qkv,
                 __nv_bfloat16* __restrict__ outh,
                 __nv_bfloat16* __restrict__ outl)
{
    extern __shared__ __align__(16) float sm[];
    float* Qs = sm;
    float* Ks = sm + 64 * 68;
    float* Vs = sm + 2 * 64 * 68;
    u64*   Ps = (u64*)(sm + 3 * 64 * 68);

    const u32 qsb = (u32)__cvta_generic_to_shared(Qs);
    const u32 ksb = (u32)__cvta_generic_to_shared(Ks);
    const u32 vsb = (u32)__cvta_generic_to_shared(Vs);
    const u32 psb = (u32)__cvta_generic_to_shared(Ps);

    const int tid = threadIdx.x;
    const int tx = tid & 15, ty = tid >> 4;
    const int bh = blockIdx.y, b = bh >> 3, hh_ = bh & 7;
    const int q0 = blockIdx.x * BQ;

    #pragma unroll
    for (int it = 0; it < 4; it++) {
        int id = tid + 256 * it;
        int r  = id >> 4;
        int dc = (id & 15) << 2;
        float4 v = make_float4(0.f, 0.f, 0.f, 0.f);
        if (q0 + r < SS_)
            v = *(const float4*)(qkv + (size_t)(b * SS_ + q0 + r) * (3 * D_) + hh_ * DH_ + dc);
        *(float4*)&Qs[r * 68 + dc] = v;
    }

    float m[4], l[4];
    #pragma unroll
    for (int i = 0; i < 4; i++) { m[i] = -3e38f; l[i] = 0.f; }
    u64 o2[4][2];
    #pragma unroll
    for (int i = 0; i < 4; i++) { o2[i][0] = 0ull; o2[i][1] = 0ull; }

    int qhi = q0 + BQ; if (qhi > SS_) qhi = SS_;
    const int limit  = (PP_ > qhi) ? PP_ : qhi;
    const int ntiles = (limit + BKT - 1) / BKT;

    const u32 qa = qsb + (u32)ty * 1088;
    const u32 ka = ksb + (u32)tx * 272;
    const u32 pa = psb + (u32)ty * 2112;
    const u32 va = vsb + (u32)tx * 16;

    for (int t = 0; t < ntiles; t++) {
        const int kt0 = t * BKT;
        __syncthreads();
        #pragma unroll
        for (int it = 0; it < 4; it++) {
            int id = tid + 256 * it;
            int r  = id >> 4;
            int dc = (id & 15) << 2;
            int rk = kt0 + r;
            float4 vk = make_float4(0.f, 0.f, 0.f, 0.f), vv = vk;
            if (rk < SS_) {
                const float* base = qkv + (size_t)(b * SS_ + rk) * (3 * D_) + hh_ * DH_ + dc;
                vk = *(const float4*)(base + D_);
                vv = *(const float4*)(base + 2 * D_);
            }
            *(float4*)&Ks[r * 68 + dc] = vk;
            *(float4*)&Vs[r * 68 + dc] = vv;
        }
        __syncthreads();

        u64 acc[4][4];
        #pragma unroll
        for (int i = 0; i < 4; i++)
            #pragma unroll
            for (int j = 0; j < 4; j++) acc[i][j] = 0ull;

        #pragma unroll 4
        for (int d = 0; d < DH_; d += 4) {
            u64 q01[4], q23[4], k01[4], k23[4];
            #pragma unroll
            for (int i = 0; i < 4; i++)
                lds128u(q01[i], q23[i], qa + (u32)i * 272 + (u32)d * 4);
            #pragma unroll
            for (int j = 0; j < 4; j++)
                lds128u(k01[j], k23[j], ka + (u32)j * 4352 + (u32)d * 4);
            #pragma unroll
            for (int i = 0; i < 4; i++)
                #pragma unroll
                for (int j = 0; j < 4; j++) {
                    ffma2(acc[i][j], q01[i], k01[j]);
                    ffma2(acc[i][j], q23[i], k23[j]);
                }
        }

        const bool masked = (kt0 + BKT > PP_);
        float alpha[4];
        float p[4][4];
        #pragma unroll
        for (int i = 0; i < 4; i++) {
            const int qg = q0 + 4 * ty + i;
            float sc[4];
            float tmax = -3e38f;
            #pragma unroll
            for (int j = 0; j < 4; j++) {
                float2 f = unpack2(acc[i][j]);
                float s = (f.x + f.y) * 0.125f;
                if (masked) {
                    int kg = kt0 + tx + 16 * j;
                    bool ok = (kg < PP_) || ((kg <= qg) && (kg < SS_));
                    if (!ok) s = NEG_BIG;
                }
                sc[j] = s;
                tmax = fmaxf(tmax, s);
            }
            tmax = fmaxf(tmax, __shfl_xor_sync(0xffffffffu, tmax, 1));
            tmax = fmaxf(tmax, __shfl_xor_sync(0xffffffffu, tmax, 2));
            tmax = fmaxf(tmax, __shfl_xor_sync(0xffffffffu, tmax, 4));
            tmax = fmaxf(tmax, __shfl_xor_sync(0xffffffffu, tmax, 8));
            float mnew = fmaxf(m[i], tmax);
            alpha[i] = __expf(m[i] - mnew);
            float ps = 0.f;
            #pragma unroll
            for (int j = 0; j < 4; j++) {
                p[i][j] = __expf(sc[j] - mnew);
                ps += p[i][j];
            }
            ps += __shfl_xor_sync(0xffffffffu, ps, 1);
            ps += __shfl_xor_sync(0xffffffffu, ps, 2);
            ps += __shfl_xor_sync(0xffffffffu, ps, 4);
            ps += __shfl_xor_sync(0xffffffffu, ps, 8);
            l[i] = l[i] * alpha[i] + ps;
            m[i] = mnew;
        }

        #pragma unroll
        for (int i = 0; i < 4; i++)
            #pragma unroll
            for (int j = 0; j < 4; j++)
                sts64u(psb + (u32)((4 * ty + i) * 66 + tx + 16 * j) * 8,
                       bcast2(p[i][j]));
        __syncwarp();

        #pragma unroll
        for (int i = 0; i < 4; i++) {
            u64 av = bcast2(alpha[i]);
            o2[i][0] = fmul2(o2[i][0], av);
            o2[i][1] = fmul2(o2[i][1], av);
        }
        #pragma unroll 4
        for (int k = 0; k < BKT; k += 4) {
            u64 pv[4][4];
            #pragma unroll
            for (int i = 0; i < 4; i++)
                #pragma unroll
                for (int kk = 0; kk < 4; kk++)
                    pv[i][kk] = lds64u(pa + (u32)i * 528 + (u32)(k + kk) * 8);
            #pragma unroll
            for (int kk = 0; kk < 4; kk++) {
                u64 v01, v23;
                lds128u(v01, v23, va + (u32)(k + kk) * 272);
                #pragma unroll
                for (int i = 0; i < 4; i++) {
                    ffma2(o2[i][0], pv[i][kk], v01);
                    ffma2(o2[i][1], pv[i][kk], v23);
                }
            }
        }
    }

    #pragma unroll
    for (int i = 0; i < 4; i++) {
        int qg = q0 + 4 * ty + i;
        if (qg < SS_) {
            float inv = 1.f / l[i];
            float2 f0 = unpack2(o2[i][0]);
            float2 f1 = unpack2(o2[i][1]);
            float4 v = make_float4(f0.x * inv, f0.y * inv, f1.x * inv, f1.y * inv);
            uint2 hh2, ll2;
            split4(v, hh2, ll2);
            size_t off = (size_t)(b * SS_ + qg) * D_ + hh_ * DH_ + 4 * tx;
            *(uint2*)(outh + off) = hh2;
            *(uint2*)(outl + off) = ll2;
        }
    }
}

// ---------------------------------------------------------------------------
// x = LayerNorm(x + t) * g + b; writes x (f32) and hi/lo splits
// ---------------------------------------------------------------------------
__global__ __launch_bounds__(256)
void add_ln_kernel(float* __restrict__ x, const float* __restrict__ t,
                   const float* __restrict__ g, const float* __restrict__ bta,
                   __nv_bfloat16* __restrict__ xh, __nv_bfloat16* __restrict__ xl)
{
    int row  = (blockIdx.x * blockDim.x + threadIdx.x) >> 5;
    int lane = threadIdx.x & 31;
    if (row >= RR_) return;
    float* xr = x + (size_t)row * D_;
    const float* tr = t + (size_t)row * D_;
    float v[16];
    float s = 0.f;
    #pragma unroll
    for (int i = 0; i < 16; i++) {
        int d = lane + 32 * i;
        v[i] = xr[d] + tr[d];
        s += v[i];
    }
    #pragma unroll
    for (int off = 16; off > 0; off >>= 1)
        s += __shfl_xor_sync(0xffffffffu, s, off);
    float mu = s * (1.f / D_);
    float s2 = 0.f;
    #pragma unroll
    for (int i = 0; i < 16; i++) {
        float dd = v[i] - mu;
        s2 += dd * dd;
    }
    #pragma unroll
    for (int off = 16; off > 0; off >>= 1)
        s2 += __shfl_xor_sync(0xffffffffu, s2, off);
    float r = rsqrtf(s2 * (1.f / D_) + 1e-5f);
    #pragma unroll
    for (int i = 0; i < 16; i++) {
        int d = lane + 32 * i;
        float y = (v[i] - mu) * r * g[d] + bta[d];
        xr[d] = y;
        __nv_bfloat16 hi, lo;
        split1(y, hi, lo);
        xh[(size_t)row * D_ + d] = hi;
        xl[(size_t)row * D_ + d] = lo;
    }
}

// ---------------------------------------------------------------------------
// gather action rows -> bf16 splits (padded buffer; pad rows stay zero)
// ---------------------------------------------------------------------------
__global__ void gather_act(const float* __restrict__ x,
                           __nv_bfloat16* __restrict__ xh,
                           __nv_bfloat16* __restrict__ xl)
{
    int idx = blockIdx.x * blockDim.x + threadIdx.x;
    const int total = MA_ * (D_ / 4);
    if (idx >= total) return;
    int d4 = idx % (D_ / 4);
    int r  = idx / (D_ / 4);
    int b = r / AT_, a = r % AT_;
    float4 v = ((const float4*)x)[(size_t)(b * SS_ + PP_ + a) * (D_ / 4) + d4];
    uint2 hh, ll;
    split4(v, hh, ll);
    ((uint2*)xh)[idx] = hh;
    ((uint2*)xl)[idx] = ll;
}

// ---------------------------------------------------------------------------
extern "C" void kernel_launch(void* const* d_in, const int* in_sizes, int n_in,
                              void* d_out, int out_size)
{
    const float* lang = (const float*)d_in[0];
    const float* vis  = (const float*)d_in[1];
    const int*   tok  = (const int*)  d_in[2];
    const float* emb  = (const float*)d_in[3];
    const float* Wqkv = (const float*)d_in[4];
    const float* bqkv = (const float*)d_in[5];
    const float* Wo   = (const float*)d_in[6];
    const float* bo   = (const float*)d_in[7];
    const float* W1   = (const float*)d_in[8];
    const float* b1   = (const float*)d_in[9];
    const float* W2   = (const float*)d_in[10];
    const float* b2   = (const float*)d_in[11];
    const float* ln1g = (const float*)d_in[12];
    const float* ln1b = (const float*)d_in[13];
    const float* ln2g = (const float*)d_in[14];
    const float* ln2b = (const float*)d_in[15];
    const float* hW   = (const float*)d_in[16];
    const float* hb   = (const float*)d_in[17];
    float* out = (float*)d_out;

    float *x, *qkv, *tmp;
    __nv_bfloat16 *xh, *xl, *ath, *atl, *h1h, *h1l, *xah, *xal;
    __nv_bfloat16 *wqh, *wql, *woh, *wol, *w1h, *w1l, *w2h, *w2l, *hwh, *hwl;
    cudaGetSymbolAddress((void**)&x,   g_x);
    cudaGetSymbolAddress((void**)&qkv, g_qkv);
    cudaGetSymbolAddress((void**)&tmp, g_tmp);
    cudaGetSymbolAddress((void**)&xh,  g_xh);  cudaGetSymbolAddress((void**)&xl,  g_xl);
    cudaGetSymbolAddress((void**)&ath, g_ath); cudaGetSymbolAddress((void**)&atl, g_atl);
    cudaGetSymbolAddress((void**)&h1h, g_h1h); cudaGetSymbolAddress((void**)&h1l, g_h1l);
    cudaGetSymbolAddress((void**)&xah, g_xah); cudaGetSymbolAddress((void**)&xal, g_xal);
    cudaGetSymbolAddress((void**)&wqh, g_wqh); cudaGetSymbolAddress((void**)&wql, g_wql);
    cudaGetSymbolAddress((void**)&woh, g_woh); cudaGetSymbolAddress((void**)&wol, g_wol);
    cudaGetSymbolAddress((void**)&w1h, g_w1h); cudaGetSymbolAddress((void**)&w1l, g_w1l);
    cudaGetSymbolAddress((void**)&w2h, g_w2h); cudaGetSymbolAddress((void**)&w2l, g_w2l);
    cudaGetSymbolAddress((void**)&hwh, g_hwh); cudaGetSymbolAddress((void**)&hwl, g_hwl);

    cudaFuncSetAttribute(attn_kernel,
                         cudaFuncAttributeMaxDynamicSharedMemorySize, AT_SMEM);
    cudaFuncSetAttribute(gemm_mma<false, false>,
                         cudaFuncAttributeMaxDynamicSharedMemorySize, GM_SMEM);
    cudaFuncSetAttribute(gemm_mma<true, true>,
                         cudaFuncAttributeMaxDynamicSharedMemorySize, GM_SMEM);

    // weight conversions
    const int nWq = NL_ * 3 * D_ * D_, nWo = NL_ * D_ * D_;
    const int nW1 = NL_ * 4 * D_ * D_, nHW = VV_ * D_;
    conv_split<<<(nWq / 4 + 255) / 256, 256>>>((const float4*)Wqkv, (uint2*)wqh, (uint2*)wql, nWq / 4);
    conv_split<<<(nWo / 4 + 255) / 256, 256>>>((const float4*)Wo,   (uint2*)woh, (uint2*)wol, nWo / 4);
    conv_split<<<(nW1 / 4 + 255) / 256, 256>>>((const float4*)W1,   (uint2*)w1h, (uint2*)w1l, nW1 / 4);
    conv_split<<<(nW1 / 4 + 255) / 256, 256>>>((const float4*)W2,   (uint2*)w2h, (uint2*)w2l, nW1 / 4);
    conv_split<<<(nHW / 4 + 255) / 256, 256>>>((const float4*)hW,   (uint2*)hwh, (uint2*)hwl, nHW / 4);

    embed_kernel<<<(RR_ * (D_ / 4) + 255) / 256, 256>>>(lang, vis, tok, emb, x, xh, xl);

    const int MT = RR_ / 128;   // 146
    for (int l = 0; l < NL_; l++) {
        gemm_mma<false, false><<<dim3(12, MT), 256, GM_SMEM>>>(
            xh, xl, wqh + (size_t)l * 3 * D_ * D_, wql + (size_t)l * 3 * D_ * D_,
            bqkv + (size_t)l * 3 * D_, qkv, nullptr, nullptr, RR_, 3 * D_, D_);
        attn_kernel<<<dim3((SS_ + BQ - 1) / BQ, BB_ * NH_), 256, AT_SMEM>>>(qkv, ath, atl);
        gemm_mma<false, false><<<dim3(4, MT), 256, GM_SMEM>>>(
            ath, atl, woh + (size_t)l * D_ * D_, wol + (size_t)l * D_ * D_,
            bo + (size_t)l * D_, tmp, nullptr, nullptr, RR_, D_, D_);
        add_ln_kernel<<<(RR_ + 7) / 8, 256>>>(x, tmp,
            ln1g + (size_t)l * D_, ln1b + (size_t)l * D_, xh, xl);
        gemm_mma<true, true><<<dim3(16, MT), 256, GM_SMEM>>>(
            xh, xl, w1h + (size_t)l * 4 * D_ * D_, w1l + (size_t)l * 4 * D_ * D_,
            b1 + (size_t)l * 4 * D_, nullptr, h1h, h1l, RR_, 4 * D_, D_);
        gemm_mma<false, false><<<dim3(4, MT), 256, GM_SMEM>>>(
            h1h, h1l, w2h + (size_t)l * D_ * 4 * D_, w2l + (size_t)l * D_ * 4 * D_,
            b2 + (size_t)l * D_, tmp, nullptr, nullptr, RR_, D_, 4 * D_);
        add_ln_kernel<<<(RR_ + 7) / 8, 256>>>(x, tmp,
            ln2g + (size_t)l * D_, ln2b + (size_t)l * D_, xh, xl);
    }

    gather_act<<<(MA_ * (D_ / 4) + 255) / 256, 256>>>(x, xah, xal);
    gemm_mma<false, false><<<dim3(2, 17), 256, GM_SMEM>>>(
        xah, xal, hwh, hwl, hb, out, nullptr, nullptr, MA_, VV_, D_);
}

// round 9
// speedup vs baseline: 2.8712x; 1.0044x over previous
#include <cuda_runtime.h>
#include <cuda_bf16.h>
#include <cstdint>

// ---------------------------------------------------------------------------
// RT1Transformer, round 9: split-bf16 mma.sync GEMMs with 3-stage cp.async
// pipeline (one __syncthreads per K-chunk, copy overlapped with mma).
// Flash-attention fp32-FFMA2. Producers emit bf16 hi/lo splits.
// ---------------------------------------------------------------------------

#define NEG_BIG (-1e9f)

typedef unsigned long long u64;
typedef unsigned int u32;

constexpr int D_  = 512;
constexpr int DH_ = 64;
constexpr int NH_ = 8;
constexpr int NL_ = 4;
constexpr int VV_ = 256;
constexpr int BB_ = 32;
constexpr int KT_ = 32;
constexpr int VT_ = 486;
constexpr int AT_ = 66;
constexpr int SS_ = KT_ + VT_ + AT_;   // 584
constexpr int PP_ = KT_ + VT_;         // 518
constexpr int RR_ = BB_ * SS_;         // 18688 (= 146*128)
constexpr int MA_ = BB_ * AT_;         // 2112
constexpr int MAP_ = 17 * 128;         // 2176 padded

// fp32 scratch
__device__ float g_x   [(size_t)RR_ * D_];
__device__ float g_qkv [(size_t)RR_ * 3 * D_];
__device__ float g_tmp [(size_t)RR_ * D_];
// bf16 hi/lo activation splits
__device__ __nv_bfloat16 g_xh  [(size_t)RR_ * D_];
__device__ __nv_bfloat16 g_xl  [(size_t)RR_ * D_];
__device__ __nv_bfloat16 g_ath [(size_t)RR_ * D_];
__device__ __nv_bfloat16 g_atl [(size_t)RR_ * D_];
__device__ __nv_bfloat16 g_h1h [(size_t)RR_ * 4 * D_];
__device__ __nv_bfloat16 g_h1l [(size_t)RR_ * 4 * D_];
__device__ __nv_bfloat16 g_xah [(size_t)MAP_ * D_];   // zero-init padding rows
__device__ __nv_bfloat16 g_xal [(size_t)MAP_ * D_];
// bf16 hi/lo weights
__device__ __nv_bfloat16 g_wqh [(size_t)NL_ * 3 * D_ * D_];
__device__ __nv_bfloat16 g_wql [(size_t)NL_ * 3 * D_ * D_];
__device__ __nv_bfloat16 g_woh [(size_t)NL_ * D_ * D_];
__device__ __nv_bfloat16 g_wol [(size_t)NL_ * D_ * D_];
__device__ __nv_bfloat16 g_w1h [(size_t)NL_ * 4 * D_ * D_];
__device__ __nv_bfloat16 g_w1l [(size_t)NL_ * 4 * D_ * D_];
__device__ __nv_bfloat16 g_w2h [(size_t)NL_ * 4 * D_ * D_];
__device__ __nv_bfloat16 g_w2l [(size_t)NL_ * 4 * D_ * D_];
__device__ __nv_bfloat16 g_hwh [(size_t)VV_ * D_];
__device__ __nv_bfloat16 g_hwl [(size_t)VV_ * D_];

// ---- packed f32x2 helpers (attention) --------------------------------------
__device__ __forceinline__ u64 bcast2(float x) {
    u64 r; asm("mov.b64 %0, {%1, %1};" : "=l"(r) : "f"(x)); return r;
}
__device__ __forceinline__ float2 unpack2(u64 v) {
    float2 f; asm("mov.b64 {%0, %1}, %2;" : "=f"(f.x), "=f"(f.y) : "l"(v)); return f;
}
__device__ __forceinline__ void ffma2(u64& d, u64 a, u64 b) {
    asm("fma.rn.f32x2 %0, %1, %2, %0;" : "+l"(d) : "l"(a), "l"(b));
}
__device__ __forceinline__ u64 fmul2(u64 a, u64 b) {
    u64 r; asm("mul.rn.f32x2 %0, %1, %2;" : "=l"(r) : "l"(a), "l"(b)); return r;
}
__device__ __forceinline__ void lds128u(u64& a, u64& b, u32 addr) {
    asm volatile("ld.shared.v2.u64 {%0, %1}, [%2];" : "=l"(a), "=l"(b) : "r"(addr));
}
__device__ __forceinline__ u64 lds64u(u32 addr) {
    u64 r; asm volatile("ld.shared.u64 %0, [%1];" : "=l"(r) : "r"(addr)); return r;
}
__device__ __forceinline__ void sts64u(u32 addr, u64 v) {
    asm volatile("st.shared.u64 [%0], %1;" :: "r"(addr), "l"(v));
}

// ---- bf16 split helpers -----------------------------------------------------
__device__ __forceinline__ void split1(float v, __nv_bfloat16& h, __nv_bfloat16& l) {
    h = __float2bfloat16(v);
    l = __float2bfloat16(v - __bfloat162float(h));
}
__device__ __forceinline__ void split4(float4 v, uint2& h, uint2& l) {
    __nv_bfloat16 h0, h1, h2, h3, l0, l1, l2, l3;
    split1(v.x, h0, l0); split1(v.y, h1, l1);
    split1(v.z, h2, l2); split1(v.w, h3, l3);
    h.x = ((u32)__bfloat16_as_ushort(h1) << 16) | __bfloat16_as_ushort(h0);
    h.y = ((u32)__bfloat16_as_ushort(h3) << 16) | __bfloat16_as_ushort(h2);
    l.x = ((u32)__bfloat16_as_ushort(l1) << 16) | __bfloat16_as_ushort(l0);
    l.y = ((u32)__bfloat16_as_ushort(l3) << 16) | __bfloat16_as_ushort(l2);
}
__device__ __forceinline__ void split2(float x, float y, u32& h, u32& l) {
    __nv_bfloat16 hx, lx, hy, ly;
    split1(x, hx, lx); split1(y, hy, ly);
    h = ((u32)__bfloat16_as_ushort(hy) << 16) | __bfloat16_as_ushort(hx);
    l = ((u32)__bfloat16_as_ushort(ly) << 16) | __bfloat16_as_ushort(lx);
}

// ---- mma.sync primitives ----------------------------------------------------
__device__ __forceinline__ void ldm4(u32& r0, u32& r1, u32& r2, u32& r3, u32 a) {
    asm volatile("ldmatrix.sync.aligned.m8n8.x4.shared.b16 {%0,%1,%2,%3}, [%4];"
                 : "=r"(r0), "=r"(r1), "=r"(r2), "=r"(r3) : "r"(a));
}
__device__ __forceinline__ void mma16816(float* d, const u32* a, u32 b0, u32 b1) {
    asm volatile("mma.sync.aligned.m16n8k16.row.col.f32.bf16.bf16.f32 "
                 "{%0,%1,%2,%3}, {%4,%5,%6,%7}, {%8,%9}, {%0,%1,%2,%3};"
                 : "+f"(d[0]), "+f"(d[1]), "+f"(d[2]), "+f"(d[3])
                 : "r"(a[0]), "r"(a[1]), "r"(a[2]), "r"(a[3]), "r"(b0), "r"(b1));
}
__device__ __forceinline__ void cp16(u32 dst, const void* src) {
    asm volatile("cp.async.cg.shared.global [%0], [%1], 16;" :: "r"(dst), "l"(src));
}
__device__ __forceinline__ void cp_commit() { asm volatile("cp.async.commit_group;"); }
__device__ __forceinline__ void cp_wait1()  { asm volatile("cp.async.wait_group 1;"); }

// ---------------------------------------------------------------------------
// split-bf16 mma.sync GEMM: C[m,n] = sum_k A[m,k]B[n,k] + bias[n]
// C ~= Ah Bh^T + Ah Bl^T + Al Bh^T (fp32 accum).
// Tile 128x128, BK=64, 8 warps (4M x 2N), warp tile 32x64.
// 3-stage cp.async pipeline: ONE __syncthreads per K-chunk; the copy of
// chunk c+2 overlaps the mma block of chunk c.
// smem rows 128B, swizzle off = row*128 + ((k ^ (row&7))*16): conflict-free.
// ---------------------------------------------------------------------------
constexpr u32 GM_TILE  = 16384;           // 128 rows x 128 B
constexpr u32 GM_STAGE = 4 * GM_TILE;     // Ah, Al, Bh, Bl
constexpr int GM_SMEM  = 1024 + 3 * (int)GM_STAGE;   // align slack + 3 stages

template<bool RELU, bool OUTBF16>
__global__ __launch_bounds__(256)
void gemm_mma(const __nv_bfloat16* __restrict__ Ah, const __nv_bfloat16* __restrict__ Al,
              const __nv_bfloat16* __restrict__ Bh, const __nv_bfloat16* __restrict__ Bl,
              const float* __restrict__ bias,
              float* __restrict__ Cf,
              __nv_bfloat16* __restrict__ Ch, __nv_bfloat16* __restrict__ Cl,
              int M, int N, int K)
{
    extern __shared__ char dynraw[];
    const u32 raw = (u32)__cvta_generic_to_shared(dynraw);
    const u32 sb  = (raw + 1023u) & ~1023u;

    const int tid  = threadIdx.x;
    const int lane = tid & 31;
    const int warp = tid >> 5;
    const int wm   = warp >> 1;     // 0..3
    const int wn   = warp & 1;      // 0..1
    const int m0 = blockIdx.y * 128;
    const int n0 = blockIdx.x * 128;

    const __nv_bfloat16* tp[4] = {Ah, Al, Bh, Bl};
    const int rb[4] = {m0, m0, n0, n0};

    float acc[2][8][4];
    #pragma unroll
    for (int i = 0; i < 2; i++)
        #pragma unroll
        for (int j = 0; j < 8; j++)
            #pragma unroll
            for (int q = 0; q < 4; q++) acc[i][j][q] = 0.f;

    // per-thread load coords: 16 chunks of 16B per stage (4 per tile)
    const int lrow = tid >> 3;           // 0..31 (+32*j)
    const int lk   = tid & 7;            // 16B chunk in row

    const int NC = K >> 6;

    // fill(stage, chunk)
    auto fill = [&](int stage, int chunk) {
        const u32 stb = sb + (u32)stage * GM_STAGE;
        const int k0 = chunk << 6;
        #pragma unroll
        for (int o = 0; o < 4; o++) {
            const __nv_bfloat16* bp = tp[o];
            const int r0 = rb[o];
            const u32 tb = stb + (u32)o * GM_TILE;
            #pragma unroll
            for (int j = 0; j < 4; j++) {
                const int row = lrow + 32 * j;
                const u32 dst = tb + (u32)(row * 128 + ((lk ^ (row & 7)) * 16));
                cp16(dst, bp + (size_t)(r0 + row) * K + k0 + lk * 8);
            }
        }
    };

    fill(0, 0); cp_commit();
    fill(1, 1); cp_commit();

    int s = 0, sn = 2;   // compute stage, next fill stage (rotating mod 3)
    for (int c = 0; c < NC; c++) {
        // groups in flight: chunks c and c+1; after wait <=1 pending, chunk c ready
        cp_wait1();
        __syncthreads();   // also orders refill of stage sn vs its readers (iter c-1)
        if (c + 2 < NC) fill(sn, c + 2);
        cp_commit();

        const u32 stb = sb + (u32)s * GM_STAGE;
        #pragma unroll
        for (int h = 0; h < 4; h++) {
            // A fragments (hi, lo): 2 m16 tiles
            u32 ah[2][4], al[2][4];
            #pragma unroll
            for (int i = 0; i < 2; i++) {
                const int row = wm * 32 + i * 16 + (lane & 15);
                const int ch  = 2 * h + (lane >> 4);
                const u32 off = (u32)(row * 128 + ((ch ^ (row & 7)) * 16));
                ldm4(ah[i][0], ah[i][1], ah[i][2], ah[i][3], stb + off);
                ldm4(al[i][0], al[i][1], al[i][2], al[i][3], stb + GM_TILE + off);
            }
            // B fragments (hi, lo): 8 n8 tiles via 4 x4 loads each
            u32 bh[8][2], bl[8][2];
            #pragma unroll
            for (int g = 0; g < 4; g++) {
                const int row = wn * 64 + g * 16 + (lane & 7) + ((lane >> 4) << 3);
                const int ch  = 2 * h + ((lane >> 3) & 1);
                const u32 off = (u32)(row * 128 + ((ch ^ (row & 7)) * 16));
                ldm4(bh[2 * g][0], bh[2 * g][1], bh[2 * g + 1][0], bh[2 * g + 1][1],
                     stb + 2 * GM_TILE + off);
                ldm4(bl[2 * g][0], bl[2 * g][1], bl[2 * g + 1][0], bl[2 * g + 1][1],
                     stb + 3 * GM_TILE + off);
            }
            #pragma unroll
            for (int i = 0; i < 2; i++)
                #pragma unroll
                for (int j = 0; j < 8; j++) {
                    mma16816(acc[i][j], ah[i], bh[j][0], bh[j][1]);
                    mma16816(acc[i][j], ah[i], bl[j][0], bl[j][1]);
                    mma16816(acc[i][j], al[i], bh[j][0], bh[j][1]);
                }
        }
        s  = (s  == 2) ? 0 : s + 1;
        sn = (sn == 2) ? 0 : sn + 1;
    }

    // epilogue: fragment (i, j): rows m0+wm*32+i*16+lane/4 (+8), col n0+wn*64+j*8+(lane&3)*2
    #pragma unroll
    for (int i = 0; i < 2; i++) {
        const int r0 = m0 + wm * 32 + i * 16 + (lane >> 2);
        #pragma unroll
        for (int j = 0; j < 8; j++) {
            const int col = n0 + wn * 64 + j * 8 + (lane & 3) * 2;
            const float2 bb = *(const float2*)(bias + col);
            float v0 = acc[i][j][0] + bb.x, v1 = acc[i][j][1] + bb.y;
            float v2 = acc[i][j][2] + bb.x, v3 = acc[i][j][3] + bb.y;
            if (RELU) {
                v0 = fmaxf(v0, 0.f); v1 = fmaxf(v1, 0.f);
                v2 = fmaxf(v2, 0.f); v3 = fmaxf(v3, 0.f);
            }
            if (r0 < M) {
                if (OUTBF16) {
                    u32 hh, ll; split2(v0, v1, hh, ll);
                    *(u32*)(Ch + (size_t)r0 * N + col) = hh;
                    *(u32*)(Cl + (size_t)r0 * N + col) = ll;
                } else {
                    *(float2*)(Cf + (size_t)r0 * N + col) = make_float2(v0, v1);
                }
            }
            if (r0 + 8 < M) {
                if (OUTBF16) {
                    u32 hh, ll; split2(v2, v3, hh, ll);
                    *(u32*)(Ch + (size_t)(r0 + 8) * N + col) = hh;
                    *(u32*)(Cl + (size_t)(r0 + 8) * N + col) = ll;
                } else {
                    *(float2*)(Cf + (size_t)(r0 + 8) * N + col) = make_float2(v2, v3);
                }
            }
        }
    }
}

// ---------------------------------------------------------------------------
// fp32 -> (hi, lo) bf16 conversion (weights)
// ---------------------------------------------------------------------------
__global__ void conv_split(const float4* __restrict__ s, uint2* __restrict__ h,
                           uint2* __restrict__ l, int n4)
{
    int i = blockIdx.x * blockDim.x + threadIdx.x;
    if (i >= n4) return;
    uint2 hh, ll;
    split4(s[i], hh, ll);
    h[i] = hh; l[i] = ll;
}

// ---------------------------------------------------------------------------
// Embed + concat; writes x (f32) and hi/lo splits
// ---------------------------------------------------------------------------
__global__ void embed_kernel(const float* __restrict__ lang,
                             const float* __restrict__ vis,
                             const int*   __restrict__ tok,
                             const float* __restrict__ emb,
                             float* __restrict__ x,
                             __nv_bfloat16* __restrict__ xh,
                             __nv_bfloat16* __restrict__ xl)
{
    int idx = blockIdx.x * blockDim.x + threadIdx.x;
    if (idx >= RR_ * (D_ / 4)) return;
    int d4  = idx % (D_ / 4);
    int row = idx / (D_ / 4);
    int b = row / SS_, s = row % SS_;
    float4 v;
    if (s < KT_) {
        v = ((const float4*)lang)[(size_t)(b * KT_ + s) * (D_ / 4) + d4];
    } else if (s < PP_) {
        v = ((const float4*)vis)[(size_t)(b * VT_ + (s - KT_)) * (D_ / 4) + d4];
    } else {
        int t = tok[b * AT_ + (s - PP_)];
        v = ((const float4*)emb)[(size_t)t * (D_ / 4) + d4];
    }
    ((float4*)x)[idx] = v;
    uint2 hh, ll;
    split4(v, hh, ll);
    ((uint2*)xh)[idx] = hh;
    ((uint2*)xl)[idx] = ll;
}

// ---------------------------------------------------------------------------
// Flash attention (fp32 f32x2), writes bf16 hi/lo output splits.
// ---------------------------------------------------------------------------
constexpr int BQ  = 64;
constexpr int BKT = 64;
constexpr int AT_SMEM = (3 * 64 * 68) * 4 + 64 * 66 * 8;

__global__ __launch_bounds__(256, 2)
void attn_kernel(const float* __restrict__ qkv,
                 __nv_bfloat16* __restrict__ outh,
                 __nv_bfloat16* __restrict__ outl)
{
    extern __shared__ __align__(16) float sm[];
    float* Qs = sm;
    float* Ks = sm + 64 * 68;
    float* Vs = sm + 2 * 64 * 68;
    u64*   Ps = (u64*)(sm + 3 * 64 * 68);

    const u32 qsb = (u32)__cvta_generic_to_shared(Qs);
    const u32 ksb = (u32)__cvta_generic_to_shared(Ks);
    const u32 vsb = (u32)__cvta_generic_to_shared(Vs);
    const u32 psb = (u32)__cvta_generic_to_shared(Ps);

    const int tid = threadIdx.x;
    const int tx = tid & 15, ty = tid >> 4;
    const int bh = blockIdx.y, b = bh >> 3, hh_ = bh & 7;
    const int q0 = blockIdx.x * BQ;

    #pragma unroll
    for (int it = 0; it < 4; it++) {
        int id = tid + 256 * it;
        int r  = id >> 4;
        int dc = (id & 15) << 2;
        float4 v = make_float4(0.f, 0.f, 0.f, 0.f);
        if (q0 + r < SS_)
            v = *(const float4*)(qkv + (size_t)(b * SS_ + q0 + r) * (3 * D_) + hh_ * DH_ + dc);
        *(float4*)&Qs[r * 68 + dc] = v;
    }

    float m[4], l[4];
    #pragma unroll
    for (int i = 0; i < 4; i++) { m[i] = -3e38f; l[i] = 0.f; }
    u64 o2[4][2];
    #pragma unroll
    for (int i = 0; i < 4; i++) { o2[i][0] = 0ull; o2[i][1] = 0ull; }

    int qhi = q0 + BQ; if (qhi > SS_) qhi = SS_;
    const int limit  = (PP_ > qhi) ? PP_ : qhi;
    const int ntiles = (limit + BKT - 1) / BKT;

    const u32 qa = qsb + (u32)ty * 1088;
    const u32 ka = ksb + (u32)tx * 272;
    const u32 pa = psb + (u32)ty * 2112;
    const u32 va = vsb + (u32)tx * 16;

    for (int t = 0; t < ntiles; t++) {
        const int kt0 = t * BKT;
        __syncthreads();
        #pragma unroll
        for (int it = 0; it < 4; it++) {
            int id = tid + 256 * it;
            int r  = id >> 4;
            int dc = (id & 15) << 2;
            int rk = kt0 + r;
            float4 vk = make_float4(0.f, 0.f, 0.f, 0.f), vv = vk;
            if (rk < SS_) {
                const float* base = qkv + (size_t)(b * SS_ + rk) * (3 * D_) + hh_ * DH_ + dc;
                vk = *(const float4*)(base + D_);
                vv = *(const float4*)(base + 2 * D_);
            }
            *(float4*)&Ks[r * 68 + dc] = vk;
            *(float4*)&Vs[r * 68 + dc] = vv;
        }
        __syncthreads();

        u64 acc[4][4];
        #pragma unroll
        for (int i = 0; i < 4; i++)
            #pragma unroll
            for (int j = 0; j < 4; j++) acc[i][j] = 0ull;

        #pragma unroll 4
        for (int d = 0; d < DH_; d += 4) {
            u64 q01[4], q23[4], k01[4], k23[4];
            #pragma unroll
            for (int i = 0; i < 4; i++)
                lds128u(q01[i], q23[i], qa + (u32)i * 272 + (u32)d * 4);
            #pragma unroll
            for (int j = 0; j < 4; j++)
                lds128u(k01[j], k23[j], ka + (u32)j * 4352 + (u32)d * 4);
            #pragma unroll
            for (int i = 0; i < 4; i++)
                #pragma unroll
                for (int j = 0; j < 4; j++) {
                    ffma2(acc[i][j], q01[i], k01[j]);
                    ffma2(acc[i][j], q23[i], k23[j]);
                }
        }

        const bool masked = (kt0 + BKT > PP_);
        float alpha[4];
        float p[4][4];
        #pragma unroll
        for (int i = 0; i < 4; i++) {
            const int qg = q0 + 4 * ty + i;
            float sc[4];
            float tmax = -3e38f;
            #pragma unroll
            for (int j = 0; j < 4; j++) {
                float2 f = unpack2(acc[i][j]);
                float s = (f.x + f.y) * 0.125f;
                if (masked) {
                    int kg = kt0 + tx + 16 * j;
                    bool ok = (kg < PP_) || ((kg <= qg) && (kg < SS_));
                    if (!ok) s = NEG_BIG;
                }
                sc[j] = s;
                tmax = fmaxf(tmax, s);
            }
            tmax = fmaxf(tmax, __shfl_xor_sync(0xffffffffu, tmax, 1));
            tmax = fmaxf(tmax, __shfl_xor_sync(0xffffffffu, tmax, 2));
            tmax = fmaxf(tmax, __shfl_xor_sync(0xffffffffu, tmax, 4));
            tmax = fmaxf(tmax, __shfl_xor_sync(0xffffffffu, tmax, 8));
            float mnew = fmaxf(m[i], tmax);
            alpha[i] = __expf(m[i] - mnew);
            float ps = 0.f;
            #pragma unroll
            for (int j = 0; j < 4; j++) {
                p[i][j] = __expf(sc[j] - mnew);
                ps += p[i][j];
            }
            ps += __shfl_xor_sync(0xffffffffu, ps, 1);
            ps += __shfl_xor_sync(0xffffffffu, ps, 2);
            ps += __shfl_xor_sync(0xffffffffu, ps, 4);
            ps += __shfl_xor_sync(0xffffffffu, ps, 8);
            l[i] = l[i] * alpha[i] + ps;
            m[i] = mnew;
        }

        #pragma unroll
        for (int i = 0; i < 4; i++)
            #pragma unroll
            for (int j = 0; j < 4; j++)
                sts64u(psb + (u32)((4 * ty + i) * 66 + tx + 16 * j) * 8,
                       bcast2(p[i][j]));
        __syncwarp();

        #pragma unroll
        for (int i = 0; i < 4; i++) {
            u64 av = bcast2(alpha[i]);
            o2[i][0] = fmul2(o2[i][0], av);
            o2[i][1] = fmul2(o2[i][1], av);
        }
        #pragma unroll 4
        for (int k = 0; k < BKT; k += 4) {
            u64 pv[4][4];
            #pragma unroll
            for (int i = 0; i < 4; i++)
                #pragma unroll
                for (int kk = 0; kk < 4; kk++)
                    pv[i][kk] = lds64u(pa + (u32)i * 528 + (u32)(k + kk) * 8);
            #pragma unroll
            for (int kk = 0; kk < 4; kk++) {
                u64 v01, v23;
                lds128u(v01, v23, va + (u32)(k + kk) * 272);
                #pragma unroll
                for (int i = 0; i < 4; i++) {
                    ffma2(o2[i][0], pv[i][kk], v01);
                    ffma2(o2[i][1], pv[i][kk], v23);
                }
            }
        }
    }

    #pragma unroll
    for (int i = 0; i < 4; i++) {
        int qg = q0 + 4 * ty + i;
        if (qg < SS_) {
            float inv = 1.f / l[i];
            float2 f0 = unpack2(o2[i][0]);
            float2 f1 = unpack2(o2[i][1]);
            float4 v = make_float4(f0.x * inv, f0.y * inv, f1.x * inv, f1.y * inv);
            uint2 hh2, ll2;
            split4(v, hh2, ll2);
            size_t off = (size_t)(b * SS_ + qg) * D_ + hh_ * DH_ + 4 * tx;
            *(uint2*)(outh + off) = hh2;
            *(uint2*)(outl + off) = ll2;
        }
    }
}

// ---------------------------------------------------------------------------
// x = LayerNorm(x + t) * g + b; writes x (f32) and hi/lo splits
// ---------------------------------------------------------------------------
__global__ __launch_bounds__(256)
void add_ln_kernel(float* __restrict__ x, const float* __restrict__ t,
                   const float* __restrict__ g, const float* __restrict__ bta,
                   __nv_bfloat16* __restrict__ xh, __nv_bfloat16* __restrict__ xl)
{
    int row  = (blockIdx.x * blockDim.x + threadIdx.x) >> 5;
    int lane = threadIdx.x & 31;
    if (row >= RR_) return;
    float* xr = x + (size_t)row * D_;
    const float* tr = t + (size_t)row * D_;
    float v[16];
    float s = 0.f;
    #pragma unroll
    for (int i = 0; i < 16; i++) {
        int d = lane + 32 * i;
        v[i] = xr[d] + tr[d];
        s += v[i];
    }
    #pragma unroll
    for (int off = 16; off > 0; off >>= 1)
        s += __shfl_xor_sync(0xffffffffu, s, off);
    float mu = s * (1.f / D_);
    float s2 = 0.f;
    #pragma unroll
    for (int i = 0; i < 16; i++) {
        float dd = v[i] - mu;
        s2 += dd * dd;
    }
    #pragma unroll
    for (int off = 16; off > 0; off >>= 1)
        s2 += __shfl_xor_sync(0xffffffffu, s2, off);
    float r = rsqrtf(s2 * (1.f / D_) + 1e-5f);
    #pragma unroll
    for (int i = 0; i < 16; i++) {
        int d = lane + 32 * i;
        float y = (v[i] - mu) * r * g[d] + bta[d];
        xr[d] = y;
        __nv_bfloat16 hi, lo;
        split1(y, hi, lo);
        xh[(size_t)row * D_ + d] = hi;
        xl[(size_t)row * D_ + d] = lo;
    }
}

// ---------------------------------------------------------------------------
// gather action rows -> bf16 splits (padded buffer; pad rows stay zero)
// ---------------------------------------------------------------------------
__global__ void gather_act(const float* __restrict__ x,
                           __nv_bfloat16* __restrict__ xh,
                           __nv_bfloat16* __restrict__ xl)
{
    int idx = blockIdx.x * blockDim.x + threadIdx.x;
    const int total = MA_ * (D_ / 4);
    if (idx >= total) return;
    int d4 = idx % (D_ / 4);
    int r  = idx / (D_ / 4);
    int b = r / AT_, a = r % AT_;
    float4 v = ((const float4*)x)[(size_t)(b * SS_ + PP_ + a) * (D_ / 4) + d4];
    uint2 hh, ll;
    split4(v, hh, ll);
    ((uint2*)xh)[idx] = hh;
    ((uint2*)xl)[idx] = ll;
}

// ---------------------------------------------------------------------------
extern "C" void kernel_launch(void* const* d_in, const int* in_sizes, int n_in,
                              void* d_out, int out_size)
{
    const float* lang = (const float*)d_in[0];
    const float* vis  = (const float*)d_in[1];
    const int*   tok  = (const int*)  d_in[2];
    const float* emb  = (const float*)d_in[3];
    const float* Wqkv = (const float*)d_in[4];
    const float* bqkv = (const float*)d_in[5];
    const float* Wo   = (const float*)d_in[6];
    const float* bo   = (const float*)d_in[7];
    const float* W1   = (const float*)d_in[8];
    const float* b1   = (const float*)d_in[9];
    const float* W2   = (const float*)d_in[10];
    const float* b2   = (const float*)d_in[11];
    const float* ln1g = (const float*)d_in[12];
    const float* ln1b = (const float*)d_in[13];
    const float* ln2g = (const float*)d_in[14];
    const float* ln2b = (const float*)d_in[15];
    const float* hW   = (const float*)d_in[16];
    const float* hb   = (const float*)d_in[17];
    float* out = (float*)d_out;

    float *x, *qkv, *tmp;
    __nv_bfloat16 *xh, *xl, *ath, *atl, *h1h, *h1l, *xah, *xal;
    __nv_bfloat16 *wqh, *wql, *woh, *wol, *w1h, *w1l, *w2h, *w2l, *hwh, *hwl;
    cudaGetSymbolAddress((void**)&x,   g_x);
    cudaGetSymbolAddress((void**)&qkv, g_qkv);
    cudaGetSymbolAddress((void**)&tmp, g_tmp);
    cudaGetSymbolAddress((void**)&xh,  g_xh);  cudaGetSymbolAddress((void**)&xl,  g_xl);
    cudaGetSymbolAddress((void**)&ath, g_ath); cudaGetSymbolAddress((void**)&atl, g_atl);
    cudaGetSymbolAddress((void**)&h1h, g_h1h); cudaGetSymbolAddress((void**)&h1l, g_h1l);
    cudaGetSymbolAddress((void**)&xah, g_xah); cudaGetSymbolAddress((void**)&xal, g_xal);
    cudaGetSymbolAddress((void**)&wqh, g_wqh); cudaGetSymbolAddress((void**)&wql, g_wql);
    cudaGetSymbolAddress((void**)&woh, g_woh); cudaGetSymbolAddress((void**)&wol, g_wol);
    cudaGetSymbolAddress((void**)&w1h, g_w1h); cudaGetSymbolAddress((void**)&w1l, g_w1l);
    cudaGetSymbolAddress((void**)&w2h, g_w2h); cudaGetSymbolAddress((void**)&w2l, g_w2l);
    cudaGetSymbolAddress((void**)&hwh, g_hwh); cudaGetSymbolAddress((void**)&hwl, g_hwl);

    cudaFuncSetAttribute(attn_kernel,
                         cudaFuncAttributeMaxDynamicSharedMemorySize, AT_SMEM);
    cudaFuncSetAttribute(gemm_mma<false, false>,
                         cudaFuncAttributeMaxDynamicSharedMemorySize, GM_SMEM);
    cudaFuncSetAttribute(gemm_mma<true, true>,
                         cudaFuncAttributeMaxDynamicSharedMemorySize, GM_SMEM);

    // weight conversions
    const int nWq = NL_ * 3 * D_ * D_, nWo = NL_ * D_ * D_;
    const int nW1 = NL_ * 4 * D_ * D_, nHW = VV_ * D_;
    conv_split<<<(nWq / 4 + 255) / 256, 256>>>((const float4*)Wqkv, (uint2*)wqh, (uint2*)wql, nWq / 4);
    conv_split<<<(nWo / 4 + 255) / 256, 256>>>((const float4*)Wo,   (uint2*)woh, (uint2*)wol, nWo / 4);
    conv_split<<<(nW1 / 4 + 255) / 256, 256>>>((const float4*)W1,   (uint2*)w1h, (uint2*)w1l, nW1 / 4);
    conv_split<<<(nW1 / 4 + 255) / 256, 256>>>((const float4*)W2,   (uint2*)w2h, (uint2*)w2l, nW1 / 4);
    conv_split<<<(nHW / 4 + 255) / 256, 256>>>((const float4*)hW,   (uint2*)hwh, (uint2*)hwl, nHW / 4);

    embed_kernel<<<(RR_ * (D_ / 4) + 255) / 256, 256>>>(lang, vis, tok, emb, x, xh, xl);

    const int MT = RR_ / 128;   // 146
    for (int l = 0; l < NL_; l++) {
        gemm_mma<false, false><<<dim3(12, MT), 256, GM_SMEM>>>(
            xh, xl, wqh + (size_t)l * 3 * D_ * D_, wql + (size_t)l * 3 * D_ * D_,
            bqkv + (size_t)l * 3 * D_, qkv, nullptr, nullptr, RR_, 3 * D_, D_);
        attn_kernel<<<dim3((SS_ + BQ - 1) / BQ, BB_ * NH_), 256, AT_SMEM>>>(qkv, ath, atl);
        gemm_mma<false, false><<<dim3(4, MT), 256, GM_SMEM>>>(
            ath, atl, woh + (size_t)l * D_ * D_, wol + (size_t)l * D_ * D_,
            bo + (size_t)l * D_, tmp, nullptr, nullptr, RR_, D_, D_);
        add_ln_kernel<<<(RR_ + 7) / 8, 256>>>(x, tmp,
            ln1g + (size_t)l * D_, ln1b + (size_t)l * D_, xh, xl);
        gemm_mma<true, true><<<dim3(16, MT), 256, GM_SMEM>>>(
            xh, xl, w1h + (size_t)l * 4 * D_ * D_, w1l + (size_t)l * 4 * D_ * D_,
            b1 + (size_t)l * 4 * D_, nullptr, h1h, h1l, RR_, 4 * D_, D_);
        gemm_mma<false, false><<<dim3(4, MT), 256, GM_SMEM>>>(
            h1h, h1l, w2h + (size_t)l * D_ * 4 * D_, w2l + (size_t)l * D_ * 4 * D_,
            b2 + (size_t)l * D_, tmp, nullptr, nullptr, RR_, D_, 4 * D_);
        add_ln_kernel<<<(RR_ + 7) / 8, 256>>>(x, tmp,
            ln2g + (size_t)l * D_, ln2b + (size_t)l * D_, xh, xl);
    }

    gather_act<<<(MA_ * (D_ / 4) + 255) / 256, 256>>>(x, xah, xal);
    gemm_mma<false, false><<<dim3(2, 17), 256, GM_SMEM>>>(
        xah, xal, hwh, hwl, hb, out, nullptr, nullptr, MA_, VV_, D_);
}

// round 11
// speedup vs baseline: 2.8947x; 1.0082x over previous
#include <cuda_runtime.h>
#include <cuda_bf16.h>
#include <cstdint>

// ---------------------------------------------------------------------------
// RT1Transformer, round 11 (= round 10 resubmitted after broker infra failure):
// split-bf16 mma.sync GEMMs, 512 threads (16 warps, 4/SMSP) to test the
// latency-bound hypothesis; launch order arranged so the QKV GEMM is launch #5
// (ncu -s 5 profiles it). Flash-attention fp32-FFMA2.
// ---------------------------------------------------------------------------

#define NEG_BIG (-1e9f)

typedef unsigned long long u64;
typedef unsigned int u32;

constexpr int D_  = 512;
constexpr int DH_ = 64;
constexpr int NH_ = 8;
constexpr int NL_ = 4;
constexpr int VV_ = 256;
constexpr int BB_ = 32;
constexpr int KT_ = 32;
constexpr int VT_ = 486;
constexpr int AT_ = 66;
constexpr int SS_ = KT_ + VT_ + AT_;   // 584
constexpr int PP_ = KT_ + VT_;         // 518
constexpr int RR_ = BB_ * SS_;         // 18688 (= 146*128)
constexpr int MA_ = BB_ * AT_;         // 2112
constexpr int MAP_ = 17 * 128;         // 2176 padded

// fp32 scratch
__device__ float g_x   [(size_t)RR_ * D_];
__device__ float g_qkv [(size_t)RR_ * 3 * D_];
__device__ float g_tmp [(size_t)RR_ * D_];
// bf16 hi/lo activation splits
__device__ __nv_bfloat16 g_xh  [(size_t)RR_ * D_];
__device__ __nv_bfloat16 g_xl  [(size_t)RR_ * D_];
__device__ __nv_bfloat16 g_ath [(size_t)RR_ * D_];
__device__ __nv_bfloat16 g_atl [(size_t)RR_ * D_];
__device__ __nv_bfloat16 g_h1h [(size_t)RR_ * 4 * D_];
__device__ __nv_bfloat16 g_h1l [(size_t)RR_ * 4 * D_];
__device__ __nv_bfloat16 g_xah [(size_t)MAP_ * D_];   // zero-init padding rows
__device__ __nv_bfloat16 g_xal [(size_t)MAP_ * D_];
// bf16 hi/lo weights
__device__ __nv_bfloat16 g_wqh [(size_t)NL_ * 3 * D_ * D_];
__device__ __nv_bfloat16 g_wql [(size_t)NL_ * 3 * D_ * D_];
__device__ __nv_bfloat16 g_woh [(size_t)NL_ * D_ * D_];
__device__ __nv_bfloat16 g_wol [(size_t)NL_ * D_ * D_];
__device__ __nv_bfloat16 g_w1h [(size_t)NL_ * 4 * D_ * D_];
__device__ __nv_bfloat16 g_w1l [(size_t)NL_ * 4 * D_ * D_];
__device__ __nv_bfloat16 g_w2h [(size_t)NL_ * 4 * D_ * D_];
__device__ __nv_bfloat16 g_w2l [(size_t)NL_ * 4 * D_ * D_];
__device__ __nv_bfloat16 g_hwh [(size_t)VV_ * D_];
__device__ __nv_bfloat16 g_hwl [(size_t)VV_ * D_];

// ---- packed f32x2 helpers (attention) --------------------------------------
__device__ __forceinline__ u64 bcast2(float x) {
    u64 r; asm("mov.b64 %0, {%1, %1};" : "=l"(r) : "f"(x)); return r;
}
__device__ __forceinline__ float2 unpack2(u64 v) {
    float2 f; asm("mov.b64 {%0, %1}, %2;" : "=f"(f.x), "=f"(f.y) : "l"(v)); return f;
}
__device__ __forceinline__ void ffma2(u64& d, u64 a, u64 b) {
    asm("fma.rn.f32x2 %0, %1, %2, %0;" : "+l"(d) : "l"(a), "l"(b));
}
__device__ __forceinline__ u64 fmul2(u64 a, u64 b) {
    u64 r; asm("mul.rn.f32x2 %0, %1, %2;" : "=l"(r) : "l"(a), "l"(b)); return r;
}
__device__ __forceinline__ void lds128u(u64& a, u64& b, u32 addr) {
    asm volatile("ld.shared.v2.u64 {%0, %1}, [%2];" : "=l"(a), "=l"(b) : "r"(addr));
}
__device__ __forceinline__ u64 lds64u(u32 addr) {
    u64 r; asm volatile("ld.shared.u64 %0, [%1];" : "=l"(r) : "r"(addr)); return r;
}
__device__ __forceinline__ void sts64u(u32 addr, u64 v) {
    asm volatile("st.shared.u64 [%0], %1;" :: "r"(addr), "l"(v));
}

// ---- bf16 split helpers -----------------------------------------------------
__device__ __forceinline__ void split1(float v, __nv_bfloat16& h, __nv_bfloat16& l) {
    h = __float2bfloat16(v);
    l = __float2bfloat16(v - __bfloat162float(h));
}
__device__ __forceinline__ void split4(float4 v, uint2& h, uint2& l) {
    __nv_bfloat16 h0, h1, h2, h3, l0, l1, l2, l3;
    split1(v.x, h0, l0); split1(v.y, h1, l1);
    split1(v.z, h2, l2); split1(v.w, h3, l3);
    h.x = ((u32)__bfloat16_as_ushort(h1) << 16) | __bfloat16_as_ushort(h0);
    h.y = ((u32)__bfloat16_as_ushort(h3) << 16) | __bfloat16_as_ushort(h2);
    l.x = ((u32)__bfloat16_as_ushort(l1) << 16) | __bfloat16_as_ushort(l0);
    l.y = ((u32)__bfloat16_as_ushort(l3) << 16) | __bfloat16_as_ushort(l2);
}
__device__ __forceinline__ void split2(float x, float y, u32& h, u32& l) {
    __nv_bfloat16 hx, lx, hy, ly;
    split1(x, hx, lx); split1(y, hy, ly);
    h = ((u32)__bfloat16_as_ushort(hy) << 16) | __bfloat16_as_ushort(hx);
    l = ((u32)__bfloat16_as_ushort(ly) << 16) | __bfloat16_as_ushort(lx);
}

// ---- mma.sync primitives ----------------------------------------------------
__device__ __forceinline__ void ldm4(u32& r0, u32& r1, u32& r2, u32& r3, u32 a) {
    asm volatile("ldmatrix.sync.aligned.m8n8.x4.shared.b16 {%0,%1,%2,%3}, [%4];"
                 : "=r"(r0), "=r"(r1), "=r"(r2), "=r"(r3) : "r"(a));
}
__device__ __forceinline__ void mma16816(float* d, const u32* a, u32 b0, u32 b1) {
    asm volatile("mma.sync.aligned.m16n8k16.row.col.f32.bf16.bf16.f32 "
                 "{%0,%1,%2,%3}, {%4,%5,%6,%7}, {%8,%9}, {%0,%1,%2,%3};"
                 : "+f"(d[0]), "+f"(d[1]), "+f"(d[2]), "+f"(d[3])
                 : "r"(a[0]), "r"(a[1]), "r"(a[2]), "r"(a[3]), "r"(b0), "r"(b1));
}
__device__ __forceinline__ void cp16(u32 dst, const void* src) {
    asm volatile("cp.async.cg.shared.global [%0], [%1], 16;" :: "r"(dst), "l"(src));
}
__device__ __forceinline__ void cp_commit() { asm volatile("cp.async.commit_group;"); }
__device__ __forceinline__ void cp_wait1()  { asm volatile("cp.async.wait_group 1;"); }

// ---------------------------------------------------------------------------
// split-bf16 mma.sync GEMM: C[m,n] = sum_k A[m,k]B[n,k] + bias[n]
// C ~= Ah Bh^T + Ah Bl^T + Al Bh^T (fp32 accum).
// Tile 128x128, BK=64, 16 warps (4M x 4N), warp tile 32x32 (4 warps/SMSP
// to hide LDSM/HMMA latency). 3-stage cp.async pipeline, one barrier/chunk.
// smem rows 128B, swizzle off = row*128 + ((k ^ (row&7))*16): conflict-free.
// ---------------------------------------------------------------------------
constexpr u32 GM_TILE  = 16384;           // 128 rows x 128 B
constexpr u32 GM_STAGE = 4 * GM_TILE;     // Ah, Al, Bh, Bl
constexpr int GM_SMEM  = 1024 + 3 * (int)GM_STAGE;   // align slack + 3 stages

template<bool RELU, bool OUTBF16>
__global__ __launch_bounds__(512)
void gemm_mma(const __nv_bfloat16* __restrict__ Ah, const __nv_bfloat16* __restrict__ Al,
              const __nv_bfloat16* __restrict__ Bh, const __nv_bfloat16* __restrict__ Bl,
              const float* __restrict__ bias,
              float* __restrict__ Cf,
              __nv_bfloat16* __restrict__ Ch, __nv_bfloat16* __restrict__ Cl,
              int M, int N, int K)
{
    extern __shared__ char dynraw[];
    const u32 raw = (u32)__cvta_generic_to_shared(dynraw);
    const u32 sb  = (raw + 1023u) & ~1023u;

    const int tid  = threadIdx.x;
    const int lane = tid & 31;
    const int warp = tid >> 5;      // 0..15
    const int wm   = warp >> 2;     // 0..3  (32 rows each)
    const int wn   = warp & 3;      // 0..3  (32 cols each)
    const int m0 = blockIdx.y * 128;
    const int n0 = blockIdx.x * 128;

    const __nv_bfloat16* tp[4] = {Ah, Al, Bh, Bl};
    const int rb[4] = {m0, m0, n0, n0};

    float acc[2][4][4];
    #pragma unroll
    for (int i = 0; i < 2; i++)
        #pragma unroll
        for (int j = 0; j < 4; j++)
            #pragma unroll
            for (int q = 0; q < 4; q++) acc[i][j][q] = 0.f;

    // per-thread load coords: 8 chunks of 16B per stage (2 per tile)
    const int lrow = tid >> 3;           // 0..63 (+64*j)
    const int lk   = tid & 7;            // 16B chunk in row

    const int NC = K >> 6;

    // fill(stage, chunk)
    auto fill = [&](int stage, int chunk) {
        const u32 stb = sb + (u32)stage * GM_STAGE;
        const int k0 = chunk << 6;
        #pragma unroll
        for (int o = 0; o < 4; o++) {
            const __nv_bfloat16* bp = tp[o];
            const int r0 = rb[o];
            const u32 tb = stb + (u32)o * GM_TILE;
            #pragma unroll
            for (int j = 0; j < 2; j++) {
                const int row = lrow + 64 * j;
                const u32 dst = tb + (u32)(row * 128 + ((lk ^ (row & 7)) * 16));
                cp16(dst, bp + (size_t)(r0 + row) * K + k0 + lk * 8);
            }
        }
    };

    fill(0, 0); cp_commit();
    fill(1, 1); cp_commit();

    int s = 0, sn = 2;   // compute stage, next fill stage (rotating mod 3)
    for (int c = 0; c < NC; c++) {
        cp_wait1();
        __syncthreads();   // orders refill of stage sn vs its readers (iter c-1)
        if (c + 2 < NC) fill(sn, c + 2);
        cp_commit();

        const u32 stb = sb + (u32)s * GM_STAGE;
        #pragma unroll
        for (int h = 0; h < 4; h++) {
            // A fragments (hi, lo): 2 m16 tiles
            u32 ah[2][4], al[2][4];
            #pragma unroll
            for (int i = 0; i < 2; i++) {
                const int row = wm * 32 + i * 16 + (lane & 15);
                const int ch  = 2 * h + (lane >> 4);
                const u32 off = (u32)(row * 128 + ((ch ^ (row & 7)) * 16));
                ldm4(ah[i][0], ah[i][1], ah[i][2], ah[i][3], stb + off);
                ldm4(al[i][0], al[i][1], al[i][2], al[i][3], stb + GM_TILE + off);
            }
            // B fragments (hi, lo): 4 n8 tiles via 2 x4 loads each
            u32 bh[4][2], bl[4][2];
            #pragma unroll
            for (int g = 0; g < 2; g++) {
                const int row = wn * 32 + g * 16 + (lane & 7) + ((lane >> 4) << 3);
                const int ch  = 2 * h + ((lane >> 3) & 1);
                const u32 off = (u32)(row * 128 + ((ch ^ (row & 7)) * 16));
                ldm4(bh[2 * g][0], bh[2 * g][1], bh[2 * g + 1][0], bh[2 * g + 1][1],
                     stb + 2 * GM_TILE + off);
                ldm4(bl[2 * g][0], bl[2 * g][1], bl[2 * g + 1][0], bl[2 * g + 1][1],
                     stb + 3 * GM_TILE + off);
            }
            #pragma unroll
            for (int i = 0; i < 2; i++)
                #pragma unroll
                for (int j = 0; j < 4; j++) {
                    mma16816(acc[i][j], ah[i], bh[j][0], bh[j][1]);
                    mma16816(acc[i][j], ah[i], bl[j][0], bl[j][1]);
                    mma16816(acc[i][j], al[i], bh[j][0], bh[j][1]);
                }
        }
        s  = (s  == 2) ? 0 : s + 1;
        sn = (sn == 2) ? 0 : sn + 1;
    }

    // epilogue: fragment (i, j): rows m0+wm*32+i*16+lane/4 (+8), col n0+wn*32+j*8+(lane&3)*2
    #pragma unroll
    for (int i = 0; i < 2; i++) {
        const int r0 = m0 + wm * 32 + i * 16 + (lane >> 2);
        #pragma unroll
        for (int j = 0; j < 4; j++) {
            const int col = n0 + wn * 32 + j * 8 + (lane & 3) * 2;
            const float2 bb = *(const float2*)(bias + col);
            float v0 = acc[i][j][0] + bb.x, v1 = acc[i][j][1] + bb.y;
            float v2 = acc[i][j][2] + bb.x, v3 = acc[i][j][3] + bb.y;
            if (RELU) {
                v0 = fmaxf(v0, 0.f); v1 = fmaxf(v1, 0.f);
                v2 = fmaxf(v2, 0.f); v3 = fmaxf(v3, 0.f);
            }
            if (r0 < M) {
                if (OUTBF16) {
                    u32 hh, ll; split2(v0, v1, hh, ll);
                    *(u32*)(Ch + (size_t)r0 * N + col) = hh;
                    *(u32*)(Cl + (size_t)r0 * N + col) = ll;
                } else {
                    *(float2*)(Cf + (size_t)r0 * N + col) = make_float2(v0, v1);
                }
            }
            if (r0 + 8 < M) {
                if (OUTBF16) {
                    u32 hh, ll; split2(v2, v3, hh, ll);
                    *(u32*)(Ch + (size_t)(r0 + 8) * N + col) = hh;
                    *(u32*)(Cl + (size_t)(r0 + 8) * N + col) = ll;
                } else {
                    *(float2*)(Cf + (size_t)(r0 + 8) * N + col) = make_float2(v2, v3);
                }
            }
        }
    }
}

// ---------------------------------------------------------------------------
// fp32 -> (hi, lo) bf16 conversion (weights)
// ---------------------------------------------------------------------------
__global__ void conv_split(const float4* __restrict__ s, uint2* __restrict__ h,
                           uint2* __restrict__ l, int n4)
{
    int i = blockIdx.x * blockDim.x + threadIdx.x;
    if (i >= n4) return;
    uint2 hh, ll;
    split4(s[i], hh, ll);
    h[i] = hh; l[i] = ll;
}

// ---------------------------------------------------------------------------
// Embed + concat; writes x (f32) and hi/lo splits
// ---------------------------------------------------------------------------
__global__ void embed_kernel(const float* __restrict__ lang,
                             const float* __restrict__ vis,
                             const int*   __restrict__ tok,
                             const float* __restrict__ emb,
                             float* __restrict__ x,
                             __nv_bfloat16* __restrict__ xh,
                             __nv_bfloat16* __restrict__ xl)
{
    int idx = blockIdx.x * blockDim.x + threadIdx.x;
    if (idx >= RR_ * (D_ / 4)) return;
    int d4  = idx % (D_ / 4);
    int row = idx / (D_ / 4);
    int b = row / SS_, s = row % SS_;
    float4 v;
    if (s < KT_) {
        v = ((const float4*)lang)[(size_t)(b * KT_ + s) * (D_ / 4) + d4];
    } else if (s < PP_) {
        v = ((const float4*)vis)[(size_t)(b * VT_ + (s - KT_)) * (D_ / 4) + d4];
    } else {
        int t = tok[b * AT_ + (s - PP_)];
        v = ((const float4*)emb)[(size_t)t * (D_ / 4) + d4];
    }
    ((float4*)x)[idx] = v;
    uint2 hh, ll;
    split4(v, hh, ll);
    ((uint2*)xh)[idx] = hh;
    ((uint2*)xl)[idx] = ll;
}

// ---------------------------------------------------------------------------
// Flash attention (fp32 f32x2), writes bf16 hi/lo output splits.
// ---------------------------------------------------------------------------
constexpr int BQ  = 64;
constexpr int BKT = 64;
constexpr int AT_SMEM = (3 * 64 * 68) * 4 + 64 * 66 * 8;

__global__ __launch_bounds__(256, 2)
void attn_kernel(const float* __restrict__ qkv,
                 __nv_bfloat16* __restrict__ outh,
                 __nv_bfloat16* __restrict__ outl)
{
    extern __shared__ __align__(16) float sm[];
    float* Qs = sm;
    float* Ks = sm + 64 * 68;
    float* Vs = sm + 2 * 64 * 68;
    u64*   Ps = (u64*)(sm + 3 * 64 * 68);

    const u32 qsb = (u32)__cvta_generic_to_shared(Qs);
    const u32 ksb = (u32)__cvta_generic_to_shared(Ks);
    const u32 vsb = (u32)__cvta_generic_to_shared(Vs);
    const u32 psb = (u32)__cvta_generic_to_shared(Ps);

    const int tid = threadIdx.x;
    const int tx = tid & 15, ty = tid >> 4;
    const int bh = blockIdx.y, b = bh >> 3, hh_ = bh & 7;
    const int q0 = blockIdx.x * BQ;

    #pragma unroll
    for (int it = 0; it < 4; it++) {
        int id = tid + 256 * it;
        int r  = id >> 4;
        int dc = (id & 15) << 2;
        float4 v = make_float4(0.f, 0.f, 0.f, 0.f);
        if (q0 + r < SS_)
            v = *(const float4*)(qkv + (size_t)(b * SS_ + q0 + r) * (3 * D_) + hh_ * DH_ + dc);
        *(float4*)&Qs[r * 68 + dc] = v;
    }

    float m[4], l[4];
    #pragma unroll
    for (int i = 0; i < 4; i++) { m[i] = -3e38f; l[i] = 0.f; }
    u64 o2[4][2];
    #pragma unroll
    for (int i = 0; i < 4; i++) { o2[i][0] = 0ull; o2[i][1] = 0ull; }

    int qhi = q0 + BQ; if (qhi > SS_) qhi = SS_;
    const int limit  = (PP_ > qhi) ? PP_ : qhi;
    const int ntiles = (limit + BKT - 1) / BKT;

    const u32 qa = qsb + (u32)ty * 1088;
    const u32 ka = ksb + (u32)tx * 272;
    const u32 pa = psb + (u32)ty * 2112;
    const u32 va = vsb + (u32)tx * 16;

    for (int t = 0; t < ntiles; t++) {
        const int kt0 = t * BKT;
        __syncthreads();
        #pragma unroll
        for (int it = 0; it < 4; it++) {
            int id = tid + 256 * it;
            int r  = id >> 4;
            int dc = (id & 15) << 2;
            int rk = kt0 + r;
            float4 vk = make_float4(0.f, 0.f, 0.f, 0.f), vv = vk;
            if (rk < SS_) {
                const float* base = qkv + (size_t)(b * SS_ + rk) * (3 * D_) + hh_ * DH_ + dc;
                vk = *(const float4*)(base + D_);
                vv = *(const float4*)(base + 2 * D_);
            }
            *(float4*)&Ks[r * 68 + dc] = vk;
            *(float4*)&Vs[r * 68 + dc] = vv;
        }
        __syncthreads();

        u64 acc[4][4];
        #pragma unroll
        for (int i = 0; i < 4; i++)
            #pragma unroll
            for (int j = 0; j < 4; j++) acc[i][j] = 0ull;

        #pragma unroll 4
        for (int d = 0; d < DH_; d += 4) {
            u64 q01[4], q23[4], k01[4], k23[4];
            #pragma unroll
            for (int i = 0; i < 4; i++)
                lds128u(q01[i], q23[i], qa + (u32)i * 272 + (u32)d * 4);
            #pragma unroll
            for (int j = 0; j < 4; j++)
                lds128u(k01[j], k23[j], ka + (u32)j * 4352 + (u32)d * 4);
            #pragma unroll
            for (int i = 0; i < 4; i++)
                #pragma unroll
                for (int j = 0; j < 4; j++) {
                    ffma2(acc[i][j], q01[i], k01[j]);
                    ffma2(acc[i][j], q23[i], k23[j]);
                }
        }

        const bool masked = (kt0 + BKT > PP_);
        float alpha[4];
        float p[4][4];
        #pragma unroll
        for (int i = 0; i < 4; i++) {
            const int qg = q0 + 4 * ty + i;
            float sc[4];
            float tmax = -3e38f;
            #pragma unroll
            for (int j = 0; j < 4; j++) {
                float2 f = unpack2(acc[i][j]);
                float s = (f.x + f.y) * 0.125f;
                if (masked) {
                    int kg = kt0 + tx + 16 * j;
                    bool ok = (kg < PP_) || ((kg <= qg) && (kg < SS_));
                    if (!ok) s = NEG_BIG;
                }
                sc[j] = s;
                tmax = fmaxf(tmax, s);
            }
            tmax = fmaxf(tmax, __shfl_xor_sync(0xffffffffu, tmax, 1));
            tmax = fmaxf(tmax, __shfl_xor_sync(0xffffffffu, tmax, 2));
            tmax = fmaxf(tmax, __shfl_xor_sync(0xffffffffu, tmax, 4));
            tmax = fmaxf(tmax, __shfl_xor_sync(0xffffffffu, tmax, 8));
            float mnew = fmaxf(m[i], tmax);
            alpha[i] = __expf(m[i] - mnew);
            float ps = 0.f;
            #pragma unroll
            for (int j = 0; j < 4; j++) {
                p[i][j] = __expf(sc[j] - mnew);
                ps += p[i][j];
            }
            ps += __shfl_xor_sync(0xffffffffu, ps, 1);
            ps += __shfl_xor_sync(0xffffffffu, ps, 2);
            ps += __shfl_xor_sync(0xffffffffu, ps, 4);
            ps += __shfl_xor_sync(0xffffffffu, ps, 8);
            l[i] = l[i] * alpha[i] + ps;
            m[i] = mnew;
        }

        #pragma unroll
        for (int i = 0; i < 4; i++)
            #pragma unroll
            for (int j = 0; j < 4; j++)
                sts64u(psb + (u32)((4 * ty + i) * 66 + tx + 16 * j) * 8,
                       bcast2(p[i][j]));
        __syncwarp();

        #pragma unroll
        for (int i = 0; i < 4; i++) {
            u64 av = bcast2(alpha[i]);
            o2[i][0] = fmul2(o2[i][0], av);
            o2[i][1] = fmul2(o2[i][1], av);
        }
        #pragma unroll 4
        for (int k = 0; k < BKT; k += 4) {
            u64 pv[4][4];
            #pragma unroll
            for (int i = 0; i < 4; i++)
                #pragma unroll
                for (int kk = 0; kk < 4; kk++)
                    pv[i][kk] = lds64u(pa + (u32)i * 528 + (u32)(k + kk) * 8);
            #pragma unroll
            for (int kk = 0; kk < 4; kk++) {
                u64 v01, v23;
                lds128u(v01, v23, va + (u32)(k + kk) * 272);
                #pragma unroll
                for (int i = 0; i < 4; i++) {
                    ffma2(o2[i][0], pv[i][kk], v01);
                    ffma2(o2[i][1], pv[i][kk], v23);
                }
            }
        }
    }

    #pragma unroll
    for (int i = 0; i < 4; i++) {
        int qg = q0 + 4 * ty + i;
        if (qg < SS_) {
            float inv = 1.f / l[i];
            float2 f0 = unpack2(o2[i][0]);
            float2 f1 = unpack2(o2[i][1]);
            float4 v = make_float4(f0.x * inv, f0.y * inv, f1.x * inv, f1.y * inv);
            uint2 hh2, ll2;
            split4(v, hh2, ll2);
            size_t off = (size_t)(b * SS_ + qg) * D_ + hh_ * DH_ + 4 * tx;
            *(uint2*)(outh + off) = hh2;
            *(uint2*)(outl + off) = ll2;
        }
    }
}

// ---------------------------------------------------------------------------
// x = LayerNorm(x + t) * g + b; writes x (f32) and hi/lo splits
// ---------------------------------------------------------------------------
__global__ __launch_bounds__(256)
void add_ln_kernel(float* __restrict__ x, const float* __restrict__ t,
                   const float* __restrict__ g, const float* __restrict__ bta,
                   __nv_bfloat16* __restrict__ xh, __nv_bfloat16* __restrict__ xl)
{
    int row  = (blockIdx.x * blockDim.x + threadIdx.x) >> 5;
    int lane = threadIdx.x & 31;
    if (row >= RR_) return;
    float* xr = x + (size_t)row * D_;
    const float* tr = t + (size_t)row * D_;
    float v[16];
    float s = 0.f;
    #pragma unroll
    for (int i = 0; i < 16; i++) {
        int d = lane + 32 * i;
        v[i] = xr[d] + tr[d];
        s += v[i];
    }
    #pragma unroll
    for (int off = 16; off > 0; off >>= 1)
        s += __shfl_xor_sync(0xffffffffu, s, off);
    float mu = s * (1.f / D_);
    float s2 = 0.f;
    #pragma unroll
    for (int i = 0; i < 16; i++) {
        float dd = v[i] - mu;
        s2 += dd * dd;
    }
    #pragma unroll
    for (int off = 16; off > 0; off >>= 1)
        s2 += __shfl_xor_sync(0xffffffffu, s2, off);
    float r = rsqrtf(s2 * (1.f / D_) + 1e-5f);
    #pragma unroll
    for (int i = 0; i < 16; i++) {
        int d = lane + 32 * i;
        float y = (v[i] - mu) * r * g[d] + bta[d];
        xr[d] = y;
        __nv_bfloat16 hi, lo;
        split1(y, hi, lo);
        xh[(size_t)row * D_ + d] = hi;
        xl[(size_t)row * D_ + d] = lo;
    }
}

// ---------------------------------------------------------------------------
// gather action rows -> bf16 splits (padded buffer; pad rows stay zero)
// ---------------------------------------------------------------------------
__global__ void gather_act(const float* __restrict__ x,
                           __nv_bfloat16* __restrict__ xh,
                           __nv_bfloat16* __restrict__ xl)
{
    int idx = blockIdx.x * blockDim.x + threadIdx.x;
    const int total = MA_ * (D_ / 4);
    if (idx >= total) return;
    int d4 = idx % (D_ / 4);
    int r  = idx / (D_ / 4);
    int b = r / AT_, a = r % AT_;
    float4 v = ((const float4*)x)[(size_t)(b * SS_ + PP_ + a) * (D_ / 4) + d4];
    uint2 hh, ll;
    split4(v, hh, ll);
    ((uint2*)xh)[idx] = hh;
    ((uint2*)xl)[idx] = ll;
}

// ---------------------------------------------------------------------------
extern "C" void kernel_launch(void* const* d_in, const int* in_sizes, int n_in,
                              void* d_out, int out_size)
{
    const float* lang = (const float*)d_in[0];
    const float* vis  = (const float*)d_in[1];
    const int*   tok  = (const int*)  d_in[2];
    const float* emb  = (const float*)d_in[3];
    const float* Wqkv = (const float*)d_in[4];
    const float* bqkv = (const float*)d_in[5];
    const float* Wo   = (const float*)d_in[6];
    const float* bo   = (const float*)d_in[7];
    const float* W1   = (const float*)d_in[8];
    const float* b1   = (const float*)d_in[9];
    const float* W2   = (const float*)d_in[10];
    const float* b2   = (const float*)d_in[11];
    const float* ln1g = (const float*)d_in[12];
    const float* ln1b = (const float*)d_in[13];
    const float* ln2g = (const float*)d_in[14];
    const float* ln2b = (const float*)d_in[15];
    const float* hW   = (const float*)d_in[16];
    const float* hb   = (const float*)d_in[17];
    float* out = (float*)d_out;

    float *x, *qkv, *tmp;
    __nv_bfloat16 *xh, *xl, *ath, *atl, *h1h, *h1l, *xah, *xal;
    __nv_bfloat16 *wqh, *wql, *woh, *wol, *w1h, *w1l, *w2h, *w2l, *hwh, *hwl;
    cudaGetSymbolAddress((void**)&x,   g_x);
    cudaGetSymbolAddress((void**)&qkv, g_qkv);
    cudaGetSymbolAddress((void**)&tmp, g_tmp);
    cudaGetSymbolAddress((void**)&xh,  g_xh);  cudaGetSymbolAddress((void**)&xl,  g_xl);
    cudaGetSymbolAddress((void**)&ath, g_ath); cudaGetSymbolAddress((void**)&atl, g_atl);
    cudaGetSymbolAddress((void**)&h1h, g_h1h); cudaGetSymbolAddress((void**)&h1l, g_h1l);
    cudaGetSymbolAddress((void**)&xah, g_xah); cudaGetSymbolAddress((void**)&xal, g_xal);
    cudaGetSymbolAddress((void**)&wqh, g_wqh); cudaGetSymbolAddress((void**)&wql, g_wql);
    cudaGetSymbolAddress((void**)&woh, g_woh); cudaGetSymbolAddress((void**)&wol, g_wol);
    cudaGetSymbolAddress((void**)&w1h, g_w1h); cudaGetSymbolAddress((void**)&w1l, g_w1l);
    cudaGetSymbolAddress((void**)&w2h, g_w2h); cudaGetSymbolAddress((void**)&w2l, g_w2l);
    cudaGetSymbolAddress((void**)&hwh, g_hwh); cudaGetSymbolAddress((void**)&hwl, g_hwl);

    cudaFuncSetAttribute(attn_kernel,
                         cudaFuncAttributeMaxDynamicSharedMemorySize, AT_SMEM);
    cudaFuncSetAttribute(gemm_mma<false, false>,
                         cudaFuncAttributeMaxDynamicSharedMemorySize, GM_SMEM);
    cudaFuncSetAttribute(gemm_mma<true, true>,
                         cudaFuncAttributeMaxDynamicSharedMemorySize, GM_SMEM);

    const int nWq = NL_ * 3 * D_ * D_, nWo = NL_ * D_ * D_;
    const int nW1 = NL_ * 4 * D_ * D_, nHW = VV_ * D_;
    const int MT = RR_ / 128;   // 146

    // Launch order arranged so the layer-0 QKV GEMM is launch index 5
    // (ncu -s 5 -c 1 profiles it).
    conv_split<<<(nWq / 4 + 255) / 256, 256>>>((const float4*)Wqkv, (uint2*)wqh, (uint2*)wql, nWq / 4);  // 0
    embed_kernel<<<(RR_ * (D_ / 4) + 255) / 256, 256>>>(lang, vis, tok, emb, x, xh, xl);                  // 1
    conv_split<<<(nWo / 4 + 255) / 256, 256>>>((const float4*)Wo,   (uint2*)woh, (uint2*)wol, nWo / 4);  // 2
    conv_split<<<(nW1 / 4 + 255) / 256, 256>>>((const float4*)W1,   (uint2*)w1h, (uint2*)w1l, nW1 / 4);  // 3
    conv_split<<<(nW1 / 4 + 255) / 256, 256>>>((const float4*)W2,   (uint2*)w2h, (uint2*)w2l, nW1 / 4);  // 4

    for (int l = 0; l < NL_; l++) {
        gemm_mma<false, false><<<dim3(12, MT), 512, GM_SMEM>>>(                                          // 5 for l=0
            xh, xl, wqh + (size_t)l * 3 * D_ * D_, wql + (size_t)l * 3 * D_ * D_,
            bqkv + (size_t)l * 3 * D_, qkv, nullptr, nullptr, RR_, 3 * D_, D_);
        attn_kernel<<<dim3((SS_ + BQ - 1) / BQ, BB_ * NH_), 256, AT_SMEM>>>(qkv, ath, atl);
        gemm_mma<false, false><<<dim3(4, MT), 512, GM_SMEM>>>(
            ath, atl, woh + (size_t)l * D_ * D_, wol + (size_t)l * D_ * D_,
            bo + (size_t)l * D_, tmp, nullptr, nullptr, RR_, D_, D_);
        add_ln_kernel<<<(RR_ + 7) / 8, 256>>>(x, tmp,
            ln1g + (size_t)l * D_, ln1b + (size_t)l * D_, xh, xl);
        gemm_mma<true, true><<<dim3(16, MT), 512, GM_SMEM>>>(
            xh, xl, w1h + (size_t)l * 4 * D_ * D_, w1l + (size_t)l * 4 * D_ * D_,
            b1 + (size_t)l * 4 * D_, nullptr, h1h, h1l, RR_, 4 * D_, D_);
        gemm_mma<false, false><<<dim3(4, MT), 512, GM_SMEM>>>(
            h1h, h1l, w2h + (size_t)l * D_ * 4 * D_, w2l + (size_t)l * D_ * 4 * D_,
            b2 + (size_t)l * D_, tmp, nullptr, nullptr, RR_, D_, 4 * D_);
        add_ln_kernel<<<(RR_ + 7) / 8, 256>>>(x, tmp,
            ln2g + (size_t)l * D_, ln2b + (size_t)l * D_, xh, xl);
    }

    conv_split<<<(nHW / 4 + 255) / 256, 256>>>((const float4*)hW, (uint2*)hwh, (uint2*)hwl, nHW / 4);
    gather_act<<<(MA_ * (D_ / 4) + 255) / 256, 256>>>(x, xah, xal);
    gemm_mma<false, false><<<dim3(2, 17), 512, GM_SMEM>>>(
        xah, xal, hwh, hwl, hb, out, nullptr, nullptr, MA_, VV_, D_);
}

// round 13
// speedup vs baseline: 3.4684x; 1.1982x over previous
#include <cuda_runtime.h>
#include <cuda_bf16.h>
#include <cstdint>

// ---------------------------------------------------------------------------
// RT1Transformer, round 13 (= round 12 resubmitted after broker infra failure):
// last-layer sparsity — layer 3's attention runs only the action q-tiles, and
// its Wo/LN/FFN/head run on a compact 2112-row (padded 2176) buffer.
// GEMMs: split-bf16 mma.sync (512 thr, 3-stage cp.async). Attn: fp32 FFMA2.
// ---------------------------------------------------------------------------

#define NEG_BIG (-1e9f)

typedef unsigned long long u64;
typedef unsigned int u32;

constexpr int D_  = 512;
constexpr int DH_ = 64;
constexpr int NH_ = 8;
constexpr int NL_ = 4;
constexpr int VV_ = 256;
constexpr int BB_ = 32;
constexpr int KT_ = 32;
constexpr int VT_ = 486;
constexpr int AT_ = 66;
constexpr int SS_ = KT_ + VT_ + AT_;   // 584
constexpr int PP_ = KT_ + VT_;         // 518
constexpr int RR_ = BB_ * SS_;         // 18688 (= 146*128)
constexpr int MA_ = BB_ * AT_;         // 2112
constexpr int MAP_ = 17 * 128;         // 2176 padded

// fp32 scratch
__device__ float g_x   [(size_t)RR_ * D_];
__device__ float g_qkv [(size_t)RR_ * 3 * D_];
__device__ float g_tmp [(size_t)RR_ * D_];
__device__ float g_cx  [(size_t)MAP_ * D_];    // compact action-row x
__device__ float g_ctmp[(size_t)MAP_ * D_];    // compact GEMM output
// bf16 hi/lo activation splits
__device__ __nv_bfloat16 g_xh  [(size_t)RR_ * D_];
__device__ __nv_bfloat16 g_xl  [(size_t)RR_ * D_];
__device__ __nv_bfloat16 g_ath [(size_t)RR_ * D_];
__device__ __nv_bfloat16 g_atl [(size_t)RR_ * D_];
__device__ __nv_bfloat16 g_h1h [(size_t)RR_ * 4 * D_];
__device__ __nv_bfloat16 g_h1l [(size_t)RR_ * 4 * D_];
__device__ __nv_bfloat16 g_cah [(size_t)MAP_ * D_];   // compact attn rows (pad stays 0)
__device__ __nv_bfloat16 g_cal [(size_t)MAP_ * D_];
__device__ __nv_bfloat16 g_cxh [(size_t)MAP_ * D_];   // compact x splits (pad stays 0)
__device__ __nv_bfloat16 g_cxl [(size_t)MAP_ * D_];
// bf16 hi/lo weights
__device__ __nv_bfloat16 g_wqh [(size_t)NL_ * 3 * D_ * D_];
__device__ __nv_bfloat16 g_wql [(size_t)NL_ * 3 * D_ * D_];
__device__ __nv_bfloat16 g_woh [(size_t)NL_ * D_ * D_];
__device__ __nv_bfloat16 g_wol [(size_t)NL_ * D_ * D_];
__device__ __nv_bfloat16 g_w1h [(size_t)NL_ * 4 * D_ * D_];
__device__ __nv_bfloat16 g_w1l [(size_t)NL_ * 4 * D_ * D_];
__device__ __nv_bfloat16 g_w2h [(size_t)NL_ * 4 * D_ * D_];
__device__ __nv_bfloat16 g_w2l [(size_t)NL_ * 4 * D_ * D_];
__device__ __nv_bfloat16 g_hwh [(size_t)VV_ * D_];
__device__ __nv_bfloat16 g_hwl [(size_t)VV_ * D_];

// ---- packed f32x2 helpers (attention) --------------------------------------
__device__ __forceinline__ u64 bcast2(float x) {
    u64 r; asm("mov.b64 %0, {%1, %1};" : "=l"(r) : "f"(x)); return r;
}
__device__ __forceinline__ float2 unpack2(u64 v) {
    float2 f; asm("mov.b64 {%0, %1}, %2;" : "=f"(f.x), "=f"(f.y) : "l"(v)); return f;
}
__device__ __forceinline__ void ffma2(u64& d, u64 a, u64 b) {
    asm("fma.rn.f32x2 %0, %1, %2, %0;" : "+l"(d) : "l"(a), "l"(b));
}
__device__ __forceinline__ u64 fmul2(u64 a, u64 b) {
    u64 r; asm("mul.rn.f32x2 %0, %1, %2;" : "=l"(r) : "l"(a), "l"(b)); return r;
}
__device__ __forceinline__ void lds128u(u64& a, u64& b, u32 addr) {
    asm volatile("ld.shared.v2.u64 {%0, %1}, [%2];" : "=l"(a), "=l"(b) : "r"(addr));
}
__device__ __forceinline__ u64 lds64u(u32 addr) {
    u64 r; asm volatile("ld.shared.u64 %0, [%1];" : "=l"(r) : "r"(addr)); return r;
}
__device__ __forceinline__ void sts64u(u32 addr, u64 v) {
    asm volatile("st.shared.u64 [%0], %1;" :: "r"(addr), "l"(v));
}

// ---- bf16 split helpers -----------------------------------------------------
__device__ __forceinline__ void split1(float v, __nv_bfloat16& h, __nv_bfloat16& l) {
    h = __float2bfloat16(v);
    l = __float2bfloat16(v - __bfloat162float(h));
}
__device__ __forceinline__ void split4(float4 v, uint2& h, uint2& l) {
    __nv_bfloat16 h0, h1, h2, h3, l0, l1, l2, l3;
    split1(v.x, h0, l0); split1(v.y, h1, l1);
    split1(v.z, h2, l2); split1(v.w, h3, l3);
    h.x = ((u32)__bfloat16_as_ushort(h1) << 16) | __bfloat16_as_ushort(h0);
    h.y = ((u32)__bfloat16_as_ushort(h3) << 16) | __bfloat16_as_ushort(h2);
    l.x = ((u32)__bfloat16_as_ushort(l1) << 16) | __bfloat16_as_ushort(l0);
    l.y = ((u32)__bfloat16_as_ushort(l3) << 16) | __bfloat16_as_ushort(l2);
}
__device__ __forceinline__ void split2(float x, float y, u32& h, u32& l) {
    __nv_bfloat16 hx, lx, hy, ly;
    split1(x, hx, lx); split1(y, hy, ly);
    h = ((u32)__bfloat16_as_ushort(hy) << 16) | __bfloat16_as_ushort(hx);
    l = ((u32)__bfloat16_as_ushort(ly) << 16) | __bfloat16_as_ushort(lx);
}

// ---- mma.sync primitives ----------------------------------------------------
__device__ __forceinline__ void ldm4(u32& r0, u32& r1, u32& r2, u32& r3, u32 a) {
    asm volatile("ldmatrix.sync.aligned.m8n8.x4.shared.b16 {%0,%1,%2,%3}, [%4];"
                 : "=r"(r0), "=r"(r1), "=r"(r2), "=r"(r3) : "r"(a));
}
__device__ __forceinline__ void mma16816(float* d, const u32* a, u32 b0, u32 b1) {
    asm volatile("mma.sync.aligned.m16n8k16.row.col.f32.bf16.bf16.f32 "
                 "{%0,%1,%2,%3}, {%4,%5,%6,%7}, {%8,%9}, {%0,%1,%2,%3};"
                 : "+f"(d[0]), "+f"(d[1]), "+f"(d[2]), "+f"(d[3])
                 : "r"(a[0]), "r"(a[1]), "r"(a[2]), "r"(a[3]), "r"(b0), "r"(b1));
}
__device__ __forceinline__ void cp16(u32 dst, const void* src) {
    asm volatile("cp.async.cg.shared.global [%0], [%1], 16;" :: "r"(dst), "l"(src));
}
__device__ __forceinline__ void cp_commit() { asm volatile("cp.async.commit_group;"); }
__device__ __forceinline__ void cp_wait1()  { asm volatile("cp.async.wait_group 1;"); }

// ---------------------------------------------------------------------------
// split-bf16 mma.sync GEMM (512 threads, 16 warps 4x4, 3-stage cp.async)
// ---------------------------------------------------------------------------
constexpr u32 GM_TILE  = 16384;
constexpr u32 GM_STAGE = 4 * GM_TILE;
constexpr int GM_SMEM  = 1024 + 3 * (int)GM_STAGE;

template<bool RELU, bool OUTBF16>
__global__ __launch_bounds__(512)
void gemm_mma(const __nv_bfloat16* __restrict__ Ah, const __nv_bfloat16* __restrict__ Al,
              const __nv_bfloat16* __restrict__ Bh, const __nv_bfloat16* __restrict__ Bl,
              const float* __restrict__ bias,
              float* __restrict__ Cf,
              __nv_bfloat16* __restrict__ Ch, __nv_bfloat16* __restrict__ Cl,
              int M, int N, int K)
{
    extern __shared__ char dynraw[];
    const u32 raw = (u32)__cvta_generic_to_shared(dynraw);
    const u32 sb  = (raw + 1023u) & ~1023u;

    const int tid  = threadIdx.x;
    const int lane = tid & 31;
    const int warp = tid >> 5;
    const int wm   = warp >> 2;
    const int wn   = warp & 3;
    const int m0 = blockIdx.y * 128;
    const int n0 = blockIdx.x * 128;

    const __nv_bfloat16* tp[4] = {Ah, Al, Bh, Bl};
    const int rb[4] = {m0, m0, n0, n0};

    float acc[2][4][4];
    #pragma unroll
    for (int i = 0; i < 2; i++)
        #pragma unroll
        for (int j = 0; j < 4; j++)
            #pragma unroll
            for (int q = 0; q < 4; q++) acc[i][j][q] = 0.f;

    const int lrow = tid >> 3;
    const int lk   = tid & 7;
    const int NC = K >> 6;

    auto fill = [&](int stage, int chunk) {
        const u32 stb = sb + (u32)stage * GM_STAGE;
        const int k0 = chunk << 6;
        #pragma unroll
        for (int o = 0; o < 4; o++) {
            const __nv_bfloat16* bp = tp[o];
            const int r0 = rb[o];
            const u32 tb = stb + (u32)o * GM_TILE;
            #pragma unroll
            for (int j = 0; j < 2; j++) {
                const int row = lrow + 64 * j;
                const u32 dst = tb + (u32)(row * 128 + ((lk ^ (row & 7)) * 16));
                cp16(dst, bp + (size_t)(r0 + row) * K + k0 + lk * 8);
            }
        }
    };

    fill(0, 0); cp_commit();
    fill(1, 1); cp_commit();

    int s = 0, sn = 2;
    for (int c = 0; c < NC; c++) {
        cp_wait1();
        __syncthreads();
        if (c + 2 < NC) fill(sn, c + 2);
        cp_commit();

        const u32 stb = sb + (u32)s * GM_STAGE;
        #pragma unroll
        for (int h = 0; h < 4; h++) {
            u32 ah[2][4], al[2][4];
            #pragma unroll
            for (int i = 0; i < 2; i++) {
                const int row = wm * 32 + i * 16 + (lane & 15);
                const int ch  = 2 * h + (lane >> 4);
                const u32 off = (u32)(row * 128 + ((ch ^ (row & 7)) * 16));
                ldm4(ah[i][0], ah[i][1], ah[i][2], ah[i][3], stb + off);
                ldm4(al[i][0], al[i][1], al[i][2], al[i][3], stb + GM_TILE + off);
            }
            u32 bh[4][2], bl[4][2];
            #pragma unroll
            for (int g = 0; g < 2; g++) {
                const int row = wn * 32 + g * 16 + (lane & 7) + ((lane >> 4) << 3);
                const int ch  = 2 * h + ((lane >> 3) & 1);
                const u32 off = (u32)(row * 128 + ((ch ^ (row & 7)) * 16));
                ldm4(bh[2 * g][0], bh[2 * g][1], bh[2 * g + 1][0], bh[2 * g + 1][1],
                     stb + 2 * GM_TILE + off);
                ldm4(bl[2 * g][0], bl[2 * g][1], bl[2 * g + 1][0], bl[2 * g + 1][1],
                     stb + 3 * GM_TILE + off);
            }
            #pragma unroll
            for (int i = 0; i < 2; i++)
                #pragma unroll
                for (int j = 0; j < 4; j++) {
                    mma16816(acc[i][j], ah[i], bh[j][0], bh[j][1]);
                    mma16816(acc[i][j], ah[i], bl[j][0], bl[j][1]);
                    mma16816(acc[i][j], al[i], bh[j][0], bh[j][1]);
                }
        }
        s  = (s  == 2) ? 0 : s + 1;
        sn = (sn == 2) ? 0 : sn + 1;
    }

    #pragma unroll
    for (int i = 0; i < 2; i++) {
        const int r0 = m0 + wm * 32 + i * 16 + (lane >> 2);
        #pragma unroll
        for (int j = 0; j < 4; j++) {
            const int col = n0 + wn * 32 + j * 8 + (lane & 3) * 2;
            const float2 bb = *(const float2*)(bias + col);
            float v0 = acc[i][j][0] + bb.x, v1 = acc[i][j][1] + bb.y;
            float v2 = acc[i][j][2] + bb.x, v3 = acc[i][j][3] + bb.y;
            if (RELU) {
                v0 = fmaxf(v0, 0.f); v1 = fmaxf(v1, 0.f);
                v2 = fmaxf(v2, 0.f); v3 = fmaxf(v3, 0.f);
            }
            if (r0 < M) {
                if (OUTBF16) {
                    u32 hh, ll; split2(v0, v1, hh, ll);
                    *(u32*)(Ch + (size_t)r0 * N + col) = hh;
                    *(u32*)(Cl + (size_t)r0 * N + col) = ll;
                } else {
                    *(float2*)(Cf + (size_t)r0 * N + col) = make_float2(v0, v1);
                }
            }
            if (r0 + 8 < M) {
                if (OUTBF16) {
                    u32 hh, ll; split2(v2, v3, hh, ll);
                    *(u32*)(Ch + (size_t)(r0 + 8) * N + col) = hh;
                    *(u32*)(Cl + (size_t)(r0 + 8) * N + col) = ll;
                } else {
                    *(float2*)(Cf + (size_t)(r0 + 8) * N + col) = make_float2(v2, v3);
                }
            }
        }
    }
}

// ---------------------------------------------------------------------------
__global__ void conv_split(const float4* __restrict__ s, uint2* __restrict__ h,
                           uint2* __restrict__ l, int n4)
{
    int i = blockIdx.x * blockDim.x + threadIdx.x;
    if (i >= n4) return;
    uint2 hh, ll;
    split4(s[i], hh, ll);
    h[i] = hh; l[i] = ll;
}

// ---------------------------------------------------------------------------
__global__ void embed_kernel(const float* __restrict__ lang,
                             const float* __restrict__ vis,
                             const int*   __restrict__ tok,
                             const float* __restrict__ emb,
                             float* __restrict__ x,
                             __nv_bfloat16* __restrict__ xh,
                             __nv_bfloat16* __restrict__ xl)
{
    int idx = blockIdx.x * blockDim.x + threadIdx.x;
    if (idx >= RR_ * (D_ / 4)) return;
    int d4  = idx % (D_ / 4);
    int row = idx / (D_ / 4);
    int b = row / SS_, s = row % SS_;
    float4 v;
    if (s < KT_) {
        v = ((const float4*)lang)[(size_t)(b * KT_ + s) * (D_ / 4) + d4];
    } else if (s < PP_) {
        v = ((const float4*)vis)[(size_t)(b * VT_ + (s - KT_)) * (D_ / 4) + d4];
    } else {
        int t = tok[b * AT_ + (s - PP_)];
        v = ((const float4*)emb)[(size_t)t * (D_ / 4) + d4];
    }
    ((float4*)x)[idx] = v;
    uint2 hh, ll;
    split4(v, hh, ll);
    ((uint2*)xh)[idx] = hh;
    ((uint2*)xl)[idx] = ll;
}

// ---------------------------------------------------------------------------
// Flash attention (fp32 f32x2), qt0 = q-tile offset (layer-3 runs tiles 8..9).
// ---------------------------------------------------------------------------
constexpr int BQ  = 64;
constexpr int BKT = 64;
constexpr int AT_SMEM = (3 * 64 * 68) * 4 + 64 * 66 * 8;

__global__ __launch_bounds__(256, 2)
void attn_kernel(const float* __restrict__ qkv,
                 __nv_bfloat16* __restrict__ outh,
                 __nv_bfloat16* __restrict__ outl,
                 int qt0)
{
    extern __shared__ __align__(16) float sm[];
    float* Qs = sm;
    float* Ks = sm + 64 * 68;
    float* Vs = sm + 2 * 64 * 68;
    u64*   Ps = (u64*)(sm + 3 * 64 * 68);

    const u32 qsb = (u32)__cvta_generic_to_shared(Qs);
    const u32 ksb = (u32)__cvta_generic_to_shared(Ks);
    const u32 vsb = (u32)__cvta_generic_to_shared(Vs);
    const u32 psb = (u32)__cvta_generic_to_shared(Ps);

    const int tid = threadIdx.x;
    const int tx = tid & 15, ty = tid >> 4;
    const int bh = blockIdx.y, b = bh >> 3, hh_ = bh & 7;
    const int q0 = (blockIdx.x + qt0) * BQ;

    #pragma unroll
    for (int it = 0; it < 4; it++) {
        int id = tid + 256 * it;
        int r  = id >> 4;
        int dc = (id & 15) << 2;
        float4 v = make_float4(0.f, 0.f, 0.f, 0.f);
        if (q0 + r < SS_)
            v = *(const float4*)(qkv + (size_t)(b * SS_ + q0 + r) * (3 * D_) + hh_ * DH_ + dc);
        *(float4*)&Qs[r * 68 + dc] = v;
    }

    float m[4], l[4];
    #pragma unroll
    for (int i = 0; i < 4; i++) { m[i] = -3e38f; l[i] = 0.f; }
    u64 o2[4][2];
    #pragma unroll
    for (int i = 0; i < 4; i++) { o2[i][0] = 0ull; o2[i][1] = 0ull; }

    int qhi = q0 + BQ; if (qhi > SS_) qhi = SS_;
    const int limit  = (PP_ > qhi) ? PP_ : qhi;
    const int ntiles = (limit + BKT - 1) / BKT;

    const u32 qa = qsb + (u32)ty * 1088;
    const u32 ka = ksb + (u32)tx * 272;
    const u32 pa = psb + (u32)ty * 2112;
    const u32 va = vsb + (u32)tx * 16;

    for (int t = 0; t < ntiles; t++) {
        const int kt0 = t * BKT;
        __syncthreads();
        #pragma unroll
        for (int it = 0; it < 4; it++) {
            int id = tid + 256 * it;
            int r  = id >> 4;
            int dc = (id & 15) << 2;
            int rk = kt0 + r;
            float4 vk = make_float4(0.f, 0.f, 0.f, 0.f), vv = vk;
            if (rk < SS_) {
                const float* base = qkv + (size_t)(b * SS_ + rk) * (3 * D_) + hh_ * DH_ + dc;
                vk = *(const float4*)(base + D_);
                vv = *(const float4*)(base + 2 * D_);
            }
            *(float4*)&Ks[r * 68 + dc] = vk;
            *(float4*)&Vs[r * 68 + dc] = vv;
        }
        __syncthreads();

        u64 acc[4][4];
        #pragma unroll
        for (int i = 0; i < 4; i++)
            #pragma unroll
            for (int j = 0; j < 4; j++) acc[i][j] = 0ull;

        #pragma unroll 4
        for (int d = 0; d < DH_; d += 4) {
            u64 q01[4], q23[4], k01[4], k23[4];
            #pragma unroll
            for (int i = 0; i < 4; i++)
                lds128u(q01[i], q23[i], qa + (u32)i * 272 + (u32)d * 4);
            #pragma unroll
            for (int j = 0; j < 4; j++)
                lds128u(k01[j], k23[j], ka + (u32)j * 4352 + (u32)d * 4);
            #pragma unroll
            for (int i = 0; i < 4; i++)
                #pragma unroll
                for (int j = 0; j < 4; j++) {
                    ffma2(acc[i][j], q01[i], k01[j]);
                    ffma2(acc[i][j], q23[i], k23[j]);
                }
        }

        const bool masked = (kt0 + BKT > PP_);
        float alpha[4];
        float p[4][4];
        #pragma unroll
        for (int i = 0; i < 4; i++) {
            const int qg = q0 + 4 * ty + i;
            float sc[4];
            float tmax = -3e38f;
            #pragma unroll
            for (int j = 0; j < 4; j++) {
                float2 f = unpack2(acc[i][j]);
                float s = (f.x + f.y) * 0.125f;
                if (masked) {
                    int kg = kt0 + tx + 16 * j;
                    bool ok = (kg < PP_) || ((kg <= qg) && (kg < SS_));
                    if (!ok) s = NEG_BIG;
                }
                sc[j] = s;
                tmax = fmaxf(tmax, s);
            }
            tmax = fmaxf(tmax, __shfl_xor_sync(0xffffffffu, tmax, 1));
            tmax = fmaxf(tmax, __shfl_xor_sync(0xffffffffu, tmax, 2));
            tmax = fmaxf(tmax, __shfl_xor_sync(0xffffffffu, tmax, 4));
            tmax = fmaxf(tmax, __shfl_xor_sync(0xffffffffu, tmax, 8));
            float mnew = fmaxf(m[i], tmax);
            alpha[i] = __expf(m[i] - mnew);
            float ps = 0.f;
            #pragma unroll
            for (int j = 0; j < 4; j++) {
                p[i][j] = __expf(sc[j] - mnew);
                ps += p[i][j];
            }
            ps += __shfl_xor_sync(0xffffffffu, ps, 1);
            ps += __shfl_xor_sync(0xffffffffu, ps, 2);
            ps += __shfl_xor_sync(0xffffffffu, ps, 4);
            ps += __shfl_xor_sync(0xffffffffu, ps, 8);
            l[i] = l[i] * alpha[i] + ps;
            m[i] = mnew;
        }

        #pragma unroll
        for (int i = 0; i < 4; i++)
            #pragma unroll
            for (int j = 0; j < 4; j++)
                sts64u(psb + (u32)((4 * ty + i) * 66 + tx + 16 * j) * 8,
                       bcast2(p[i][j]));
        __syncwarp();

        #pragma unroll
        for (int i = 0; i < 4; i++) {
            u64 av = bcast2(alpha[i]);
            o2[i][0] = fmul2(o2[i][0], av);
            o2[i][1] = fmul2(o2[i][1], av);
        }
        #pragma unroll 4
        for (int k = 0; k < BKT; k += 4) {
            u64 pv[4][4];
            #pragma unroll
            for (int i = 0; i < 4; i++)
                #pragma unroll
                for (int kk = 0; kk < 4; kk++)
                    pv[i][kk] = lds64u(pa + (u32)i * 528 + (u32)(k + kk) * 8);
            #pragma unroll
            for (int kk = 0; kk < 4; kk++) {
                u64 v01, v23;
                lds128u(v01, v23, va + (u32)(k + kk) * 272);
                #pragma unroll
                for (int i = 0; i < 4; i++) {
                    ffma2(o2[i][0], pv[i][kk], v01);
                    ffma2(o2[i][1], pv[i][kk], v23);
                }
            }
        }
    }

    #pragma unroll
    for (int i = 0; i < 4; i++) {
        int qg = q0 + 4 * ty + i;
        if (qg < SS_) {
            float inv = 1.f / l[i];
            float2 f0 = unpack2(o2[i][0]);
            float2 f1 = unpack2(o2[i][1]);
            float4 v = make_float4(f0.x * inv, f0.y * inv, f1.x * inv, f1.y * inv);
            uint2 hh2, ll2;
            split4(v, hh2, ll2);
            size_t off = (size_t)(b * SS_ + qg) * D_ + hh_ * DH_ + 4 * tx;
            *(uint2*)(outh + off) = hh2;
            *(uint2*)(outl + off) = ll2;
        }
    }
}

// ---------------------------------------------------------------------------
// x = LayerNorm(x + t) * g + b; writes x (f32) and hi/lo splits. nrows param.
// ---------------------------------------------------------------------------
__global__ __launch_bounds__(256)
void add_ln_kernel(float* __restrict__ x, const float* __restrict__ t,
                   const float* __restrict__ g, const float* __restrict__ bta,
                   __nv_bfloat16* __restrict__ xh, __nv_bfloat16* __restrict__ xl,
                   int nrows)
{
    int row  = (blockIdx.x * blockDim.x + threadIdx.x) >> 5;
    int lane = threadIdx.x & 31;
    if (row >= nrows) return;
    float* xr = x + (size_t)row * D_;
    const float* tr = t + (size_t)row * D_;
    float v[16];
    float s = 0.f;
    #pragma unroll
    for (int i = 0; i < 16; i++) {
        int d = lane + 32 * i;
        v[i] = xr[d] + tr[d];
        s += v[i];
    }
    #pragma unroll
    for (int off = 16; off > 0; off >>= 1)
        s += __shfl_xor_sync(0xffffffffu, s, off);
    float mu = s * (1.f / D_);
    float s2 = 0.f;
    #pragma unroll
    for (int i = 0; i < 16; i++) {
        float dd = v[i] - mu;
        s2 += dd * dd;
    }
    #pragma unroll
    for (int off = 16; off > 0; off >>= 1)
        s2 += __shfl_xor_sync(0xffffffffu, s2, off);
    float r = rsqrtf(s2 * (1.f / D_) + 1e-5f);
    #pragma unroll
    for (int i = 0; i < 16; i++) {
        int d = lane + 32 * i;
        float y = (v[i] - mu) * r * g[d] + bta[d];
        xr[d] = y;
        __nv_bfloat16 hi, lo;
        split1(y, hi, lo);
        xh[(size_t)row * D_ + d] = hi;
        xl[(size_t)row * D_ + d] = lo;
    }
}

// ---------------------------------------------------------------------------
// gather action rows of att splits + x into compact buffers (pad rows untouched)
// ---------------------------------------------------------------------------
__global__ void gather_ca(const __nv_bfloat16* __restrict__ ath,
                          const __nv_bfloat16* __restrict__ atl,
                          const float* __restrict__ x,
                          __nv_bfloat16* __restrict__ cah,
                          __nv_bfloat16* __restrict__ cal,
                          float* __restrict__ cx)
{
    int idx = blockIdx.x * blockDim.x + threadIdx.x;
    const int total = MA_ * (D_ / 4);
    if (idx >= total) return;
    int d4 = idx % (D_ / 4);
    int r  = idx / (D_ / 4);
    int b = r / AT_, a = r % AT_;
    size_t src = (size_t)(b * SS_ + PP_ + a) * (D_ / 4) + d4;
    ((uint2*)cah)[idx] = ((const uint2*)ath)[src];
    ((uint2*)cal)[idx] = ((const uint2*)atl)[src];
    ((float4*)cx)[idx] = ((const float4*)x)[src];
}

// ---------------------------------------------------------------------------
extern "C" void kernel_launch(void* const* d_in, const int* in_sizes, int n_in,
                              void* d_out, int out_size)
{
    const float* lang = (const float*)d_in[0];
    const float* vis  = (const float*)d_in[1];
    const int*   tok  = (const int*)  d_in[2];
    const float* emb  = (const float*)d_in[3];
    const float* Wqkv = (const float*)d_in[4];
    const float* bqkv = (const float*)d_in[5];
    const float* Wo   = (const float*)d_in[6];
    const float* bo   = (const float*)d_in[7];
    const float* W1   = (const float*)d_in[8];
    const float* b1   = (const float*)d_in[9];
    const float* W2   = (const float*)d_in[10];
    const float* b2   = (const float*)d_in[11];
    const float* ln1g = (const float*)d_in[12];
    const float* ln1b = (const float*)d_in[13];
    const float* ln2g = (const float*)d_in[14];
    const float* ln2b = (const float*)d_in[15];
    const float* hW   = (const float*)d_in[16];
    const float* hb   = (const float*)d_in[17];
    float* out = (float*)d_out;

    float *x, *qkv, *tmp, *cx, *ctmp;
    __nv_bfloat16 *xh, *xl, *ath, *atl, *h1h, *h1l, *cah, *cal, *cxh, *cxl;
    __nv_bfloat16 *wqh, *wql, *woh, *wol, *w1h, *w1l, *w2h, *w2l, *hwh, *hwl;
    cudaGetSymbolAddress((void**)&x,    g_x);
    cudaGetSymbolAddress((void**)&qkv,  g_qkv);
    cudaGetSymbolAddress((void**)&tmp,  g_tmp);
    cudaGetSymbolAddress((void**)&cx,   g_cx);
    cudaGetSymbolAddress((void**)&ctmp, g_ctmp);
    cudaGetSymbolAddress((void**)&xh,  g_xh);  cudaGetSymbolAddress((void**)&xl,  g_xl);
    cudaGetSymbolAddress((void**)&ath, g_ath); cudaGetSymbolAddress((void**)&atl, g_atl);
    cudaGetSymbolAddress((void**)&h1h, g_h1h); cudaGetSymbolAddress((void**)&h1l, g_h1l);
    cudaGetSymbolAddress((void**)&cah, g_cah); cudaGetSymbolAddress((void**)&cal, g_cal);
    cudaGetSymbolAddress((void**)&cxh, g_cxh); cudaGetSymbolAddress((void**)&cxl, g_cxl);
    cudaGetSymbolAddress((void**)&wqh, g_wqh); cudaGetSymbolAddress((void**)&wql, g_wql);
    cudaGetSymbolAddress((void**)&woh, g_woh); cudaGetSymbolAddress((void**)&wol, g_wol);
    cudaGetSymbolAddress((void**)&w1h, g_w1h); cudaGetSymbolAddress((void**)&w1l, g_w1l);
    cudaGetSymbolAddress((void**)&w2h, g_w2h); cudaGetSymbolAddress((void**)&w2l, g_w2l);
    cudaGetSymbolAddress((void**)&hwh, g_hwh); cudaGetSymbolAddress((void**)&hwl, g_hwl);

    cudaFuncSetAttribute(attn_kernel,
                         cudaFuncAttributeMaxDynamicSharedMemorySize, AT_SMEM);
    cudaFuncSetAttribute(gemm_mma<false, false>,
                         cudaFuncAttributeMaxDynamicSharedMemorySize, GM_SMEM);
    cudaFuncSetAttribute(gemm_mma<true, true>,
                         cudaFuncAttributeMaxDynamicSharedMemorySize, GM_SMEM);

    const int nWq = NL_ * 3 * D_ * D_, nWo = NL_ * D_ * D_;
    const int nW1 = NL_ * 4 * D_ * D_, nHW = VV_ * D_;
    const int MT = RR_ / 128;   // 146

    conv_split<<<(nWq / 4 + 255) / 256, 256>>>((const float4*)Wqkv, (uint2*)wqh, (uint2*)wql, nWq / 4);  // 0
    embed_kernel<<<(RR_ * (D_ / 4) + 255) / 256, 256>>>(lang, vis, tok, emb, x, xh, xl);                  // 1
    conv_split<<<(nWo / 4 + 255) / 256, 256>>>((const float4*)Wo,   (uint2*)woh, (uint2*)wol, nWo / 4);  // 2
    conv_split<<<(nW1 / 4 + 255) / 256, 256>>>((const float4*)W1,   (uint2*)w1h, (uint2*)w1l, nW1 / 4);  // 3
    conv_split<<<(nW1 / 4 + 255) / 256, 256>>>((const float4*)W2,   (uint2*)w2h, (uint2*)w2l, nW1 / 4);  // 4

    // layers 0..2: full
    for (int l = 0; l < NL_ - 1; l++) {
        gemm_mma<false, false><<<dim3(12, MT), 512, GM_SMEM>>>(                                          // 5 for l=0
            xh, xl, wqh + (size_t)l * 3 * D_ * D_, wql + (size_t)l * 3 * D_ * D_,
            bqkv + (size_t)l * 3 * D_, qkv, nullptr, nullptr, RR_, 3 * D_, D_);
        attn_kernel<<<dim3((SS_ + BQ - 1) / BQ, BB_ * NH_), 256, AT_SMEM>>>(qkv, ath, atl, 0);
        gemm_mma<false, false><<<dim3(4, MT), 512, GM_SMEM>>>(
            ath, atl, woh + (size_t)l * D_ * D_, wol + (size_t)l * D_ * D_,
            bo + (size_t)l * D_, tmp, nullptr, nullptr, RR_, D_, D_);
        add_ln_kernel<<<(RR_ + 7) / 8, 256>>>(x, tmp,
            ln1g + (size_t)l * D_, ln1b + (size_t)l * D_, xh, xl, RR_);
        gemm_mma<true, true><<<dim3(16, MT), 512, GM_SMEM>>>(
            xh, xl, w1h + (size_t)l * 4 * D_ * D_, w1l + (size_t)l * 4 * D_ * D_,
            b1 + (size_t)l * 4 * D_, nullptr, h1h, h1l, RR_, 4 * D_, D_);
        gemm_mma<false, false><<<dim3(4, MT), 512, GM_SMEM>>>(
            h1h, h1l, w2h + (size_t)l * D_ * 4 * D_, w2l + (size_t)l * D_ * 4 * D_,
            b2 + (size_t)l * D_, tmp, nullptr, nullptr, RR_, D_, 4 * D_);
        add_ln_kernel<<<(RR_ + 7) / 8, 256>>>(x, tmp,
            ln2g + (size_t)l * D_, ln2b + (size_t)l * D_, xh, xl, RR_);
    }

    // layer 3: attention only for action q-tiles; post-attn on compact rows
    {
        const int l = NL_ - 1;
        const int CMT = MAP_ / 128;   // 17
        gemm_mma<false, false><<<dim3(12, MT), 512, GM_SMEM>>>(
            xh, xl, wqh + (size_t)l * 3 * D_ * D_, wql + (size_t)l * 3 * D_ * D_,
            bqkv + (size_t)l * 3 * D_, qkv, nullptr, nullptr, RR_, 3 * D_, D_);
        // q-tiles 8..9 cover rows 512..583 (action rows 518..583)
        attn_kernel<<<dim3(2, BB_ * NH_), 256, AT_SMEM>>>(qkv, ath, atl, 8);
        gather_ca<<<(MA_ * (D_ / 4) + 255) / 256, 256>>>(ath, atl, x, cah, cal, cx);
        gemm_mma<false, false><<<dim3(4, CMT), 512, GM_SMEM>>>(
            cah, cal, woh + (size_t)l * D_ * D_, wol + (size_t)l * D_ * D_,
            bo + (size_t)l * D_, ctmp, nullptr, nullptr, MA_, D_, D_);
        add_ln_kernel<<<(MA_ + 7) / 8, 256>>>(cx, ctmp,
            ln1g + (size_t)l * D_, ln1b + (size_t)l * D_, cxh, cxl, MA_);
        gemm_mma<true, true><<<dim3(16, CMT), 512, GM_SMEM>>>(
            cxh, cxl, w1h + (size_t)l * 4 * D_ * D_, w1l + (size_t)l * 4 * D_ * D_,
            b1 + (size_t)l * 4 * D_, nullptr, h1h, h1l, MA_, 4 * D_, D_);
        gemm_mma<false, false><<<dim3(4, CMT), 512, GM_SMEM>>>(
            h1h, h1l, w2h + (size_t)l * D_ * 4 * D_, w2l + (size_t)l * D_ * 4 * D_,
            b2 + (size_t)l * D_, ctmp, nullptr, nullptr, MA_, D_, 4 * D_);
        add_ln_kernel<<<(MA_ + 7) / 8, 256>>>(cx, ctmp,
            ln2g + (size_t)l * D_, ln2b + (size_t)l * D_, cxh, cxl, MA_);
    }

    conv_split<<<(nHW / 4 + 255) / 256, 256>>>((const float4*)hW, (uint2*)hwh, (uint2*)hwl, nHW / 4);
    gemm_mma<false, false><<<dim3(2, 17), 512, GM_SMEM>>>(
        cxh, cxl, hwh, hwl, hb, out, nullptr, nullptr, MA_, VV_, D_);
}